// round 10
// baseline (speedup 1.0000x reference)
#include <cuda_runtime.h>
#include <cuda_bf16.h>
#include <cstdint>

#define B_  16
#define T_  8192
#define TP_ 512
#define E_  256
#define M_TOT (B_*TP_ + T_)     // 16384 GEMM rows: 8192 enc + 8192 pe
#define FULLMASK 0xFFFFFFFFu

// ---------------- device scratch (allocations are forbidden) ----------------
__device__ __align__(16) float          g_S [B_*TP_*E_];   // enc + enc@W_pos   (8 MB)
__device__ __align__(16) float          g_P [T_*E_];       // pe@W_pos + b_pos  (8 MB)
__device__ __align__(16) float          g_pe[T_*E_];       // sinusoid PE       (8 MB)
__device__ __align__(16) int            g_idx[B_*T_];      // aligner indices   (512 KB)
__device__ __align__(16) __nv_bfloat16  gBhi[E_*E_];       // W^T hi (128 KB)
__device__ __align__(16) __nv_bfloat16  gBlo[E_*E_];       // W^T lo (128 KB)

// ---------------- helpers ----------------
__device__ __forceinline__ uint32_t smem_u32(const void* p) {
    uint32_t a;
    asm("{ .reg .u64 t; cvta.to.shared.u64 t, %1; cvt.u32.u64 %0, t; }" : "=r"(a) : "l"(p));
    return a;
}
// SW64 swizzle: 64-byte rows, XOR bits [5:4] with bits [8:7]
#define SWZ64(x) ((x) ^ (((x) >> 3) & 0x30))

__device__ __forceinline__ void ldsm_x4(uint32_t& r0, uint32_t& r1, uint32_t& r2,
                                        uint32_t& r3, uint32_t addr) {
    asm volatile("ldmatrix.sync.aligned.m8n8.x4.shared.b16 {%0,%1,%2,%3}, [%4];"
                 : "=r"(r0), "=r"(r1), "=r"(r2), "=r"(r3) : "r"(addr));
}
__device__ __forceinline__ void mma_bf16(float* c, const uint32_t* a,
                                         uint32_t b0, uint32_t b1) {
    asm volatile(
        "mma.sync.aligned.m16n8k16.row.col.f32.bf16.bf16.f32 "
        "{%0,%1,%2,%3}, {%4,%5,%6,%7}, {%8,%9}, {%0,%1,%2,%3};"
        : "+f"(c[0]), "+f"(c[1]), "+f"(c[2]), "+f"(c[3])
        : "r"(a[0]), "r"(a[1]), "r"(a[2]), "r"(a[3]), "r"(b0), "r"(b1));
}
__device__ __forceinline__ uint32_t pack_bf2(float a, float b) {
    __nv_bfloat162 h(__float2bfloat16_rn(a), __float2bfloat16_rn(b));
    return *reinterpret_cast<uint32_t*>(&h);
}
__device__ __forceinline__ uint32_t pack_lo2(float a, float b) {
    __nv_bfloat16 ha = __float2bfloat16_rn(a), hb = __float2bfloat16_rn(b);
    return pack_bf2(a - __bfloat162float(ha), b - __bfloat162float(hb));
}

// =====================================================================
// Kernel 1 (prep):
//   blocks [0,256)   : sinusoid PE (fp32) via rotation trick
//   blocks [256,272) : parallel aligner (prefix-sum + validate, exact)
//   blocks [272,400) : W_pos transpose + bf16 hi/lo split
// =====================================================================
__global__ void __launch_bounds__(512) prep_kernel(const int* __restrict__ align_phone,
                                                   const int* __restrict__ text_phone,
                                                   const float* __restrict__ Wpos)
{
    int bid = blockIdx.x, tid = threadIdx.x;

    if (bid < 256) {
        int g  = bid * 512 + tid;                  // [0, 131072)
        int i  = g & 127;
        int t0 = (g >> 7) * 8;
        const float NEGC = -0.03597789202637730f;  // -ln(10000)/E
        float div = expf((float)(2*i) * NEGC);
        float s, c, sd, cd;
        sincosf((float)t0 * div, &s, &c);
        sincosf(div, &sd, &cd);
        float2* row = ((float2*)g_pe) + (size_t)t0*128 + i;
        #pragma unroll
        for (int r = 0; r < 8; r++) {
            row[(size_t)r*128] = make_float2(s, c);
            float s2 = fmaf(s, cd,  c*sd);
            float c2 = fmaf(c, cd, -s*sd);
            s = s2; c = c2;
        }
        return;
    }
    if (bid >= 272) {
        int idx = (bid - 272) * 512 + tid;         // [0, 65536)
        int k = idx >> 8, n = idx & 255;
        float w2 = Wpos[idx];
        __nv_bfloat16 wh = __float2bfloat16_rn(w2);
        gBhi[n*E_ + k] = wh;
        gBlo[n*E_ + k] = __float2bfloat16_rn(w2 - __bfloat162float(wh));
        return;
    }

    // ---------------- parallel aligner: block handles batch b ----------------
    __shared__ short stx[TP_];
    __shared__ int   wsum[16];
    __shared__ int   s_ok;
    int b = bid - 256;
    const int* arow = align_phone + (size_t)b * T_;
    int*       orow = g_idx       + (size_t)b * T_;

    for (int j = tid; j < TP_; j += 512) stx[j] = (short)text_phone[b*TP_ + j];
    if (tid == 0) s_ok = 1;
    __syncthreads();

    int base = tid * 16;
    int v[16];
    #pragma unroll
    for (int q = 0; q < 4; q++)
        *(int4*)&v[q*4] = *(const int4*)&arow[base + q*4];
    int prev = (base == 0) ? v[0] : arow[base - 1];

    unsigned cmask = 0;
    int cnt = 0;
    #pragma unroll
    for (int j = 0; j < 16; j++) {
        int c = (v[j] != prev) ? 1 : 0;
        if (base + j == 0) c = 0;
        cmask |= ((unsigned)c) << j;
        cnt += c;
        prev = v[j];
    }

    int lane = tid & 31, wId = tid >> 5;
    int incl = cnt;
    #pragma unroll
    for (int off = 1; off < 32; off <<= 1) {
        int nv = __shfl_up_sync(FULLMASK, incl, off);
        if (lane >= off) incl += nv;
    }
    if (lane == 31) wsum[wId] = incl;
    __syncthreads();
    if (tid == 0) {
        int a = 0;
        #pragma unroll
        for (int i = 0; i < 16; i++) { int t2 = wsum[i]; wsum[i] = a; a += t2; }
    }
    __syncthreads();
    int run = wsum[wId] + incl - cnt;

    bool ok = (base != 0) || (v[0] == (int)stx[0]);
    int outv[16];
    #pragma unroll
    for (int j = 0; j < 16; j++) {
        run += (int)((cmask >> j) & 1u);
        int ind = min(run, TP_ - 1);
        outv[j] = ind;
        if (base + j != 0) ok &= ((int)stx[ind] == v[j]);
    }
    #pragma unroll
    for (int q = 0; q < 4; q++)
        *(int4*)&orow[base + q*4] = *(const int4*)&outv[q*4];

    if (!ok) atomicAnd(&s_ok, 0);
    __syncthreads();
    if (s_ok == 0 && tid == 0) {
        int ind = 0, before = (int)stx[0];
        orow[0] = 0;
        for (int t = 1; t < T_; t++) {
            int a = arow[t];
            if (a != before) { ind = min(ind + 1, TP_ - 1); before = (int)stx[ind]; }
            orow[t] = ind;
        }
    }
}

// =====================================================================
// Kernel 2: bf16-split tensor-core GEMM via mma.sync (HMMA).
// D = Ahi@Bhi^T + Alo@Bhi^T + Ahi@Blo^T, fp32 accumulate.
// CTA tile 128(M) x 128(N), grid (128, 2); 8 warps of 32x64 -> 64 acc
// regs/thread (no spills). K=256 in 8 slices of 32, double-buffered
// 64 KB smem, SW64 swizzle; A converted fp32->bf16 hi/lo in-register.
// =====================================================================
#define AHI 0
#define ALO 8192
#define BHI 16384
#define BLO 24576
#define BUFSZ 32768
#define SMEM_GEMM (2*BUFSZ)

__global__ void __launch_bounds__(256, 1) gemm_kernel(const float* __restrict__ enc,
                                                      const float* __restrict__ bpos)
{
    extern __shared__ __align__(128) char smem[];
    uint32_t sb = smem_u32(smem);

    int tid  = threadIdx.x;
    int wid  = tid >> 5, lid = tid & 31;
    int wm   = wid & 3;            // 4 m-warps of 32
    int wn   = wid >> 2;           // 2 n-warps of 64
    int g    = lid >> 2, tig = lid & 3;
    int mBase = blockIdx.x * 128;
    int nBase = blockIdx.y * 128;
    bool isEnc = (mBase < B_*TP_);
    const float4* Afp = isEnc ? (const float4*)(enc + (size_t)mBase*E_)
                              : (const float4*)(g_pe + (size_t)(mBase - B_*TP_)*E_);

    float acc[2][8][4];
    #pragma unroll
    for (int t = 0; t < 2; t++)
        #pragma unroll
        for (int u = 0; u < 8; u++)
            #pragma unroll
            for (int q = 0; q < 4; q++) acc[t][u][q] = 0.f;

    auto load_slice = [&](int kc, int bsel) {
        char* buf = smem + bsel*BUFSZ;
        #pragma unroll
        for (int i = 0; i < 4; i++) {            // A: 128 rows x 8 float4
            int idx = tid + i*256;
            int row = idx >> 3, c4 = idx & 7;
            float4 v = Afp[(size_t)row*64 + kc*8 + c4];
            uint2 hi, lo;
            hi.x = pack_bf2(v.x, v.y);  hi.y = pack_bf2(v.z, v.w);
            lo.x = pack_lo2(v.x, v.y);  lo.y = pack_lo2(v.z, v.w);
            uint32_t off = SWZ64((uint32_t)(row*64 + c4*8));
            *(uint2*)(buf + AHI + off) = hi;
            *(uint2*)(buf + ALO + off) = lo;
        }
        #pragma unroll
        for (int i = 0; i < 2; i++) {            // B hi+lo: 128 rows x 4 uint4 each
            int idx = tid + i*256;
            int row = idx >> 2, c8 = idx & 3;
            uint32_t off = SWZ64((uint32_t)(row*64 + c8*16));
            *(uint4*)(buf + BHI + off) =
                ((const uint4*)gBhi)[(size_t)(nBase + row)*32 + kc*4 + c8];
            *(uint4*)(buf + BLO + off) =
                ((const uint4*)gBlo)[(size_t)(nBase + row)*32 + kc*4 + c8];
        }
    };

    load_slice(0, 0);
    __syncthreads();

    for (int kc = 0; kc < 8; kc++) {
        if (kc + 1 < 8) load_slice(kc + 1, (kc + 1) & 1);

        uint32_t ab = sb + (kc & 1)*BUFSZ;
        #pragma unroll
        for (int ks = 0; ks < 2; ks++) {
            uint32_t ah[2][4], bh[8][2];
            #pragma unroll
            for (int t = 0; t < 2; t++) {        // A hi fragments (32 rows)
                uint32_t off = (uint32_t)((wm*32 + t*16 + (lid & 15))*64
                                          + ks*32 + ((lid >> 4) & 1)*16);
                ldsm_x4(ah[t][0], ah[t][1], ah[t][2], ah[t][3], ab + AHI + SWZ64(off));
            }
            #pragma unroll
            for (int up = 0; up < 4; up++) {     // B hi fragments (64 cols)
                uint32_t off = (uint32_t)((wn*64 + up*16 + ((lid >> 4) & 1)*8
                                           + (lid & 7))*64
                                          + ks*32 + ((lid >> 3) & 1)*16);
                ldsm_x4(bh[2*up][0], bh[2*up][1], bh[2*up+1][0], bh[2*up+1][1],
                        ab + BHI + SWZ64(off));
            }
            #pragma unroll
            for (int t = 0; t < 2; t++)          // pass 1: Ahi * Bhi
                #pragma unroll
                for (int u = 0; u < 8; u++)
                    mma_bf16(acc[t][u], ah[t], bh[u][0], bh[u][1]);

            {                                    // pass 2: Alo * Bhi
                uint32_t aw[2][4];
                #pragma unroll
                for (int t = 0; t < 2; t++) {
                    uint32_t off = (uint32_t)((wm*32 + t*16 + (lid & 15))*64
                                              + ks*32 + ((lid >> 4) & 1)*16);
                    ldsm_x4(aw[t][0], aw[t][1], aw[t][2], aw[t][3],
                            ab + ALO + SWZ64(off));
                }
                #pragma unroll
                for (int t = 0; t < 2; t++)
                    #pragma unroll
                    for (int u = 0; u < 8; u++)
                        mma_bf16(acc[t][u], aw[t], bh[u][0], bh[u][1]);
            }
            {                                    // pass 3: Ahi * Blo
                uint32_t bw[8][2];
                #pragma unroll
                for (int up = 0; up < 4; up++) {
                    uint32_t off = (uint32_t)((wn*64 + up*16 + ((lid >> 4) & 1)*8
                                               + (lid & 7))*64
                                              + ks*32 + ((lid >> 3) & 1)*16);
                    ldsm_x4(bw[2*up][0], bw[2*up][1], bw[2*up+1][0], bw[2*up+1][1],
                            ab + BLO + SWZ64(off));
                }
                #pragma unroll
                for (int t = 0; t < 2; t++)
                    #pragma unroll
                    for (int u = 0; u < 8; u++)
                        mma_bf16(acc[t][u], ah[t], bw[u][0], bw[u][1]);
            }
        }
        __syncthreads();
    }

    // ---- epilogue ----
    #pragma unroll
    for (int t = 0; t < 2; t++) {
        int rm = mBase + wm*32 + t*16 + g;
        #pragma unroll
        for (int u = 0; u < 8; u++) {
            int n  = nBase + wn*64 + u*8 + tig*2;
            int i0 = rm*128 + (n >> 1);          // float2 index, row rm
            int i1 = i0 + 8*128;                 // row rm+8
            if (isEnc) {
                float2 e0 = ((const float2*)enc)[i0];
                float2 e1 = ((const float2*)enc)[i1];
                ((float2*)g_S)[i0] = make_float2(acc[t][u][0] + e0.x,
                                                 acc[t][u][1] + e0.y);
                ((float2*)g_S)[i1] = make_float2(acc[t][u][2] + e1.x,
                                                 acc[t][u][3] + e1.y);
            } else {
                float2 bp = ((const float2*)bpos)[n >> 1];
                int j0 = i0 - B_*TP_*128;
                ((float2*)g_P)[j0]         = make_float2(acc[t][u][0] + bp.x,
                                                         acc[t][u][1] + bp.y);
                ((float2*)g_P)[j0 + 8*128] = make_float2(acc[t][u][2] + bp.x,
                                                         acc[t][u][3] + bp.y);
            }
        }
    }
}

// =====================================================================
// Kernel 3: chunk-reuse assemble.
// =====================================================================
__global__ void __launch_bounds__(256) main_kernel(const float* __restrict__ pitch,
                                                   const int*   __restrict__ beats,
                                                   const float* __restrict__ Wpitch,
                                                   const float* __restrict__ bpitch,
                                                   const float* __restrict__ embBeats,
                                                   float* __restrict__ out)
{
    __shared__ __align__(16) float sP[16*E_];     // 16 KB = 1024 float4
    __shared__ int   sidx  [256];
    __shared__ float spitch[256];
    __shared__ int   sbeats[256];

    int tid = threadIdx.x;
    int t0  = blockIdx.x * 16;
    int e4  = tid & 63;
    int rp  = tid >> 6;

    #pragma unroll
    for (int i = 0; i < 4; i++)
        ((float4*)sP)[tid + i*256] = ((const float4*)g_P)[(size_t)t0*64 + tid + i*256];
    {
        int b = tid >> 4, tt = tid & 15;
        int bt = b*T_ + t0 + tt;
        sidx[tid]   = g_idx[bt];
        spitch[tid] = pitch[bt];
        sbeats[tid] = beats[bt];
    }
    __syncthreads();

    float4 wp  = ((const float4*)Wpitch)[e4];
    float4 bp  = ((const float4*)bpitch)[e4];
    float4 eb0 = ((const float4*)embBeats)[e4];
    float4 eb1 = ((const float4*)embBeats)[64 + e4];

    #pragma unroll 4
    for (int i = 0; i < 64; i++) {
        int p  = i*4 + rp;
        int b  = p >> 4, tt = p & 15;
        int ix = sidx[p];
        float4 s  = *(const float4*)&g_S[((size_t)(b*TP_ + ix))*E_ + e4*4];
        float4 pr = ((const float4*)sP)[tt*64 + e4];
        float  pv = spitch[p];
        float4 ev = sbeats[p] ? eb1 : eb0;
        float4 o;
        o.x = s.x + pr.x + fmaf(pv, wp.x, bp.x) + ev.x;
        o.y = s.y + pr.y + fmaf(pv, wp.y, bp.y) + ev.y;
        o.z = s.z + pr.z + fmaf(pv, wp.z, bp.z) + ev.z;
        o.w = s.w + pr.w + fmaf(pv, wp.w, bp.w) + ev.w;
        ((float4*)out)[((size_t)b*T_ + t0 + tt)*64 + e4] = o;
    }
}

// =====================================================================
extern "C" void kernel_launch(void* const* d_in, const int* in_sizes, int n_in,
                              void* d_out, int out_size)
{
    const float* enc      = (const float*)d_in[0];
    const int*   align_p  = (const int*)  d_in[1];
    const int*   text_p   = (const int*)  d_in[2];
    const float* pitch    = (const float*)d_in[3];
    const int*   beats    = (const int*)  d_in[4];
    const float* W_pitch  = (const float*)d_in[5];
    const float* b_pitch  = (const float*)d_in[6];
    const float* W_pos    = (const float*)d_in[7];
    const float* b_pos    = (const float*)d_in[8];
    const float* emb_b    = (const float*)d_in[9];
    float* out = (float*)d_out;

    static int smem_set = 0;
    if (!smem_set) {
        cudaFuncSetAttribute(gemm_kernel,
                             cudaFuncAttributeMaxDynamicSharedMemorySize, SMEM_GEMM);
        smem_set = 1;
    }

    prep_kernel<<<400, 512>>>(align_p, text_p, W_pos);

    dim3 ggrid(M_TOT/128, 2);
    gemm_kernel<<<ggrid, 256, SMEM_GEMM>>>(enc, b_pos);

    main_kernel<<<T_/16, 256>>>(pitch, beats, W_pitch, b_pitch, emb_b, out);
}

// round 11
// speedup vs baseline: 1.0600x; 1.0600x over previous
#include <cuda_runtime.h>
#include <cuda_bf16.h>
#include <cstdint>

#define B_  16
#define T_  8192
#define TP_ 512
#define E_  256
#define M_TOT (B_*TP_ + T_)     // 16384 GEMM rows: 8192 enc + 8192 pe
#define FULLMASK 0xFFFFFFFFu

// ---------------- device scratch (allocations are forbidden) ----------------
__device__ __align__(16) float          g_S [B_*TP_*E_];   // enc + enc@W_pos   (8 MB)
__device__ __align__(16) float          g_P [T_*E_];       // pe@W_pos + b_pos  (8 MB)
__device__ __align__(16) float          g_pe[T_*E_];       // sinusoid PE       (8 MB)
__device__ __align__(16) int            g_idx[B_*T_];      // aligner indices   (512 KB)
__device__ __align__(16) __nv_bfloat16  gBhi[E_*E_];       // W^T hi (128 KB)
__device__ __align__(16) __nv_bfloat16  gBlo[E_*E_];       // W^T lo (128 KB)

// ---------------- helpers ----------------
__device__ __forceinline__ uint32_t smem_u32(const void* p) {
    uint32_t a;
    asm("{ .reg .u64 t; cvta.to.shared.u64 t, %1; cvt.u32.u64 %0, t; }" : "=r"(a) : "l"(p));
    return a;
}
// SW64 swizzle: 64-byte rows, XOR bits [5:4] with bits [8:7]
#define SWZ64(x) ((x) ^ (((x) >> 3) & 0x30))

__device__ __forceinline__ void ldsm_x4(uint32_t& r0, uint32_t& r1, uint32_t& r2,
                                        uint32_t& r3, uint32_t addr) {
    asm volatile("ldmatrix.sync.aligned.m8n8.x4.shared.b16 {%0,%1,%2,%3}, [%4];"
                 : "=r"(r0), "=r"(r1), "=r"(r2), "=r"(r3) : "r"(addr));
}
__device__ __forceinline__ void mma_bf16(float* c, const uint32_t* a,
                                         uint32_t b0, uint32_t b1) {
    asm volatile(
        "mma.sync.aligned.m16n8k16.row.col.f32.bf16.bf16.f32 "
        "{%0,%1,%2,%3}, {%4,%5,%6,%7}, {%8,%9}, {%0,%1,%2,%3};"
        : "+f"(c[0]), "+f"(c[1]), "+f"(c[2]), "+f"(c[3])
        : "r"(a[0]), "r"(a[1]), "r"(a[2]), "r"(a[3]), "r"(b0), "r"(b1));
}
__device__ __forceinline__ uint32_t pack_bf2(float a, float b) {
    __nv_bfloat162 h(__float2bfloat16_rn(a), __float2bfloat16_rn(b));
    return *reinterpret_cast<uint32_t*>(&h);
}
__device__ __forceinline__ uint32_t pack_lo2(float a, float b) {
    __nv_bfloat16 ha = __float2bfloat16_rn(a), hb = __float2bfloat16_rn(b);
    return pack_bf2(a - __bfloat162float(ha), b - __bfloat162float(hb));
}

// =====================================================================
// Kernel 1 (prep):
//   blocks [0,256)   : sinusoid PE (fp32) via rotation trick
//   blocks [256,272) : parallel aligner (prefix-sum + validate, exact)
//   blocks [272,400) : W_pos transpose + bf16 hi/lo split
// =====================================================================
__global__ void __launch_bounds__(512) prep_kernel(const int* __restrict__ align_phone,
                                                   const int* __restrict__ text_phone,
                                                   const float* __restrict__ Wpos)
{
    int bid = blockIdx.x, tid = threadIdx.x;

    if (bid < 256) {
        int g  = bid * 512 + tid;                  // [0, 131072)
        int i  = g & 127;
        int t0 = (g >> 7) * 8;
        const float NEGC = -0.03597789202637730f;  // -ln(10000)/E
        float div = expf((float)(2*i) * NEGC);
        float s, c, sd, cd;
        sincosf((float)t0 * div, &s, &c);
        sincosf(div, &sd, &cd);
        float2* row = ((float2*)g_pe) + (size_t)t0*128 + i;
        #pragma unroll
        for (int r = 0; r < 8; r++) {
            row[(size_t)r*128] = make_float2(s, c);
            float s2 = fmaf(s, cd,  c*sd);
            float c2 = fmaf(c, cd, -s*sd);
            s = s2; c = c2;
        }
        return;
    }
    if (bid >= 272) {
        int idx = (bid - 272) * 512 + tid;         // [0, 65536)
        int k = idx >> 8, n = idx & 255;
        float w2 = Wpos[idx];
        __nv_bfloat16 wh = __float2bfloat16_rn(w2);
        gBhi[n*E_ + k] = wh;
        gBlo[n*E_ + k] = __float2bfloat16_rn(w2 - __bfloat162float(wh));
        return;
    }

    // ---------------- parallel aligner: block handles batch b ----------------
    __shared__ short stx[TP_];
    __shared__ int   wsum[16];
    __shared__ int   s_ok;
    int b = bid - 256;
    const int* arow = align_phone + (size_t)b * T_;
    int*       orow = g_idx       + (size_t)b * T_;

    for (int j = tid; j < TP_; j += 512) stx[j] = (short)text_phone[b*TP_ + j];
    if (tid == 0) s_ok = 1;
    __syncthreads();

    int base = tid * 16;
    int v[16];
    #pragma unroll
    for (int q = 0; q < 4; q++)
        *(int4*)&v[q*4] = *(const int4*)&arow[base + q*4];
    int prev = (base == 0) ? v[0] : arow[base - 1];

    unsigned cmask = 0;
    int cnt = 0;
    #pragma unroll
    for (int j = 0; j < 16; j++) {
        int c = (v[j] != prev) ? 1 : 0;
        if (base + j == 0) c = 0;
        cmask |= ((unsigned)c) << j;
        cnt += c;
        prev = v[j];
    }

    int lane = tid & 31, wId = tid >> 5;
    int incl = cnt;
    #pragma unroll
    for (int off = 1; off < 32; off <<= 1) {
        int nv = __shfl_up_sync(FULLMASK, incl, off);
        if (lane >= off) incl += nv;
    }
    if (lane == 31) wsum[wId] = incl;
    __syncthreads();
    if (tid == 0) {
        int a = 0;
        #pragma unroll
        for (int i = 0; i < 16; i++) { int t2 = wsum[i]; wsum[i] = a; a += t2; }
    }
    __syncthreads();
    int run = wsum[wId] + incl - cnt;

    bool ok = (base != 0) || (v[0] == (int)stx[0]);
    int outv[16];
    #pragma unroll
    for (int j = 0; j < 16; j++) {
        run += (int)((cmask >> j) & 1u);
        int ind = min(run, TP_ - 1);
        outv[j] = ind;
        if (base + j != 0) ok &= ((int)stx[ind] == v[j]);
    }
    #pragma unroll
    for (int q = 0; q < 4; q++)
        *(int4*)&orow[base + q*4] = *(const int4*)&outv[q*4];

    if (!ok) atomicAnd(&s_ok, 0);
    __syncthreads();
    if (s_ok == 0 && tid == 0) {
        int ind = 0, before = (int)stx[0];
        orow[0] = 0;
        for (int t = 1; t < T_; t++) {
            int a = arow[t];
            if (a != before) { ind = min(ind + 1, TP_ - 1); before = (int)stx[ind]; }
            orow[t] = ind;
        }
    }
}

// =====================================================================
// Kernel 2: bf16-split tensor-core GEMM via mma.sync (HMMA).
// D = Ahi@Bhi^T + Alo@Bhi^T + Ahi@Blo^T, fp32 accumulate.
// CTA tile 128(M) x 256(N), grid 128 (one wave); 512 threads = 16 warps
// of 32x64 -> acc 64 regs/thread (no spills). K=256 in 8 slices of 32,
// double-buffered 96 KB smem, SW64 swizzle; A converted in-register.
// =====================================================================
#define AHI 0
#define ALO 8192
#define BHI 16384
#define BLO 32768
#define BUFSZ 49152
#define SMEM_GEMM (2*BUFSZ)

__global__ void __launch_bounds__(512, 1) gemm_kernel(const float* __restrict__ enc,
                                                      const float* __restrict__ bpos)
{
    extern __shared__ __align__(128) char smem[];
    uint32_t sb = smem_u32(smem);

    int tid  = threadIdx.x;
    int wid  = tid >> 5, lid = tid & 31;
    int wm   = wid & 3;            // 4 m-warps of 32 rows
    int wn   = wid >> 2;           // 4 n-warps of 64 cols
    int g    = lid >> 2, tig = lid & 3;
    int mBase = blockIdx.x * 128;
    bool isEnc = (mBase < B_*TP_);
    const float4* Afp = isEnc ? (const float4*)(enc + (size_t)mBase*E_)
                              : (const float4*)(g_pe + (size_t)(mBase - B_*TP_)*E_);

    float acc[2][8][4];
    #pragma unroll
    for (int t = 0; t < 2; t++)
        #pragma unroll
        for (int u = 0; u < 8; u++)
            #pragma unroll
            for (int q = 0; q < 4; q++) acc[t][u][q] = 0.f;

    auto load_slice = [&](int kc, int bsel) {
        char* buf = smem + bsel*BUFSZ;
        #pragma unroll
        for (int i = 0; i < 2; i++) {            // A: 128 rows x 8 float4
            int idx = tid + i*512;
            int row = idx >> 3, c4 = idx & 7;
            float4 v = Afp[(size_t)row*64 + kc*8 + c4];
            uint2 hi, lo;
            hi.x = pack_bf2(v.x, v.y);  hi.y = pack_bf2(v.z, v.w);
            lo.x = pack_lo2(v.x, v.y);  lo.y = pack_lo2(v.z, v.w);
            uint32_t off = SWZ64((uint32_t)(row*64 + c4*8));
            *(uint2*)(buf + AHI + off) = hi;
            *(uint2*)(buf + ALO + off) = lo;
        }
        #pragma unroll
        for (int i = 0; i < 2; i++) {            // B hi+lo: 256 rows x 4 uint4 each
            int idx = tid + i*512;
            int row = idx >> 2, c8 = idx & 3;
            uint32_t off = SWZ64((uint32_t)(row*64 + c8*16));
            *(uint4*)(buf + BHI + off) = ((const uint4*)gBhi)[(size_t)row*32 + kc*4 + c8];
            *(uint4*)(buf + BLO + off) = ((const uint4*)gBlo)[(size_t)row*32 + kc*4 + c8];
        }
    };

    load_slice(0, 0);
    __syncthreads();

    for (int kc = 0; kc < 8; kc++) {
        if (kc + 1 < 8) load_slice(kc + 1, (kc + 1) & 1);

        uint32_t ab = sb + (kc & 1)*BUFSZ;
        #pragma unroll
        for (int ks = 0; ks < 2; ks++) {
            uint32_t ah[2][4], bh[8][2];
            #pragma unroll
            for (int t = 0; t < 2; t++) {        // A hi fragments (32 rows)
                uint32_t off = (uint32_t)((wm*32 + t*16 + (lid & 15))*64
                                          + ks*32 + ((lid >> 4) & 1)*16);
                ldsm_x4(ah[t][0], ah[t][1], ah[t][2], ah[t][3], ab + AHI + SWZ64(off));
            }
            #pragma unroll
            for (int up = 0; up < 4; up++) {     // B hi fragments (64 cols)
                uint32_t off = (uint32_t)((wn*64 + up*16 + ((lid >> 4) & 1)*8
                                           + (lid & 7))*64
                                          + ks*32 + ((lid >> 3) & 1)*16);
                ldsm_x4(bh[2*up][0], bh[2*up][1], bh[2*up+1][0], bh[2*up+1][1],
                        ab + BHI + SWZ64(off));
            }
            #pragma unroll
            for (int t = 0; t < 2; t++)          // pass 1: Ahi * Bhi
                #pragma unroll
                for (int u = 0; u < 8; u++)
                    mma_bf16(acc[t][u], ah[t], bh[u][0], bh[u][1]);

            {                                    // pass 2: Alo * Bhi
                uint32_t aw[2][4];
                #pragma unroll
                for (int t = 0; t < 2; t++) {
                    uint32_t off = (uint32_t)((wm*32 + t*16 + (lid & 15))*64
                                              + ks*32 + ((lid >> 4) & 1)*16);
                    ldsm_x4(aw[t][0], aw[t][1], aw[t][2], aw[t][3],
                            ab + ALO + SWZ64(off));
                }
                #pragma unroll
                for (int t = 0; t < 2; t++)
                    #pragma unroll
                    for (int u = 0; u < 8; u++)
                        mma_bf16(acc[t][u], aw[t], bh[u][0], bh[u][1]);
            }
            {                                    // pass 3: Ahi * Blo
                uint32_t bw[8][2];
                #pragma unroll
                for (int up = 0; up < 4; up++) {
                    uint32_t off = (uint32_t)((wn*64 + up*16 + ((lid >> 4) & 1)*8
                                               + (lid & 7))*64
                                              + ks*32 + ((lid >> 3) & 1)*16);
                    ldsm_x4(bw[2*up][0], bw[2*up][1], bw[2*up+1][0], bw[2*up+1][1],
                            ab + BLO + SWZ64(off));
                }
                #pragma unroll
                for (int t = 0; t < 2; t++)
                    #pragma unroll
                    for (int u = 0; u < 8; u++)
                        mma_bf16(acc[t][u], ah[t], bw[u][0], bw[u][1]);
            }
        }
        __syncthreads();
    }

    // ---- epilogue ----
    #pragma unroll
    for (int t = 0; t < 2; t++) {
        int rm = mBase + wm*32 + t*16 + g;
        #pragma unroll
        for (int u = 0; u < 8; u++) {
            int n  = wn*64 + u*8 + tig*2;
            int i0 = rm*128 + (n >> 1);          // float2 index, row rm
            int i1 = i0 + 8*128;                 // row rm+8
            if (isEnc) {
                float2 e0 = ((const float2*)enc)[i0];
                float2 e1 = ((const float2*)enc)[i1];
                ((float2*)g_S)[i0] = make_float2(acc[t][u][0] + e0.x,
                                                 acc[t][u][1] + e0.y);
                ((float2*)g_S)[i1] = make_float2(acc[t][u][2] + e1.x,
                                                 acc[t][u][3] + e1.y);
            } else {
                float2 bp = ((const float2*)bpos)[n >> 1];
                int j0 = i0 - B_*TP_*128;
                ((float2*)g_P)[j0]         = make_float2(acc[t][u][0] + bp.x,
                                                         acc[t][u][1] + bp.y);
                ((float2*)g_P)[j0 + 8*128] = make_float2(acc[t][u][2] + bp.x,
                                                         acc[t][u][3] + bp.y);
            }
        }
    }
}

// =====================================================================
// Kernel 3: chunk-reuse assemble.
// =====================================================================
__global__ void __launch_bounds__(256) main_kernel(const float* __restrict__ pitch,
                                                   const int*   __restrict__ beats,
                                                   const float* __restrict__ Wpitch,
                                                   const float* __restrict__ bpitch,
                                                   const float* __restrict__ embBeats,
                                                   float* __restrict__ out)
{
    __shared__ __align__(16) float sP[16*E_];     // 16 KB = 1024 float4
    __shared__ int   sidx  [256];
    __shared__ float spitch[256];
    __shared__ int   sbeats[256];

    int tid = threadIdx.x;
    int t0  = blockIdx.x * 16;
    int e4  = tid & 63;
    int rp  = tid >> 6;

    #pragma unroll
    for (int i = 0; i < 4; i++)
        ((float4*)sP)[tid + i*256] = ((const float4*)g_P)[(size_t)t0*64 + tid + i*256];
    {
        int b = tid >> 4, tt = tid & 15;
        int bt = b*T_ + t0 + tt;
        sidx[tid]   = g_idx[bt];
        spitch[tid] = pitch[bt];
        sbeats[tid] = beats[bt];
    }
    __syncthreads();

    float4 wp  = ((const float4*)Wpitch)[e4];
    float4 bp  = ((const float4*)bpitch)[e4];
    float4 eb0 = ((const float4*)embBeats)[e4];
    float4 eb1 = ((const float4*)embBeats)[64 + e4];

    #pragma unroll 4
    for (int i = 0; i < 64; i++) {
        int p  = i*4 + rp;
        int b  = p >> 4, tt = p & 15;
        int ix = sidx[p];
        float4 s  = *(const float4*)&g_S[((size_t)(b*TP_ + ix))*E_ + e4*4];
        float4 pr = ((const float4*)sP)[tt*64 + e4];
        float  pv = spitch[p];
        float4 ev = sbeats[p] ? eb1 : eb0;
        float4 o;
        o.x = s.x + pr.x + fmaf(pv, wp.x, bp.x) + ev.x;
        o.y = s.y + pr.y + fmaf(pv, wp.y, bp.y) + ev.y;
        o.z = s.z + pr.z + fmaf(pv, wp.z, bp.z) + ev.z;
        o.w = s.w + pr.w + fmaf(pv, wp.w, bp.w) + ev.w;
        ((float4*)out)[((size_t)b*T_ + t0 + tt)*64 + e4] = o;
    }
}

// =====================================================================
extern "C" void kernel_launch(void* const* d_in, const int* in_sizes, int n_in,
                              void* d_out, int out_size)
{
    const float* enc      = (const float*)d_in[0];
    const int*   align_p  = (const int*)  d_in[1];
    const int*   text_p   = (const int*)  d_in[2];
    const float* pitch    = (const float*)d_in[3];
    const int*   beats    = (const int*)  d_in[4];
    const float* W_pitch  = (const float*)d_in[5];
    const float* b_pitch  = (const float*)d_in[6];
    const float* W_pos    = (const float*)d_in[7];
    const float* b_pos    = (const float*)d_in[8];
    const float* emb_b    = (const float*)d_in[9];
    float* out = (float*)d_out;

    static int smem_set = 0;
    if (!smem_set) {
        cudaFuncSetAttribute(gemm_kernel,
                             cudaFuncAttributeMaxDynamicSharedMemorySize, SMEM_GEMM);
        smem_set = 1;
    }

    prep_kernel<<<400, 512>>>(align_p, text_p, W_pos);

    gemm_kernel<<<M_TOT/128, 512, SMEM_GEMM>>>(enc, b_pos);

    main_kernel<<<T_/16, 256>>>(pitch, beats, W_pitch, b_pitch, emb_b, out);
}

// round 12
// speedup vs baseline: 1.1635x; 1.0977x over previous
#include <cuda_runtime.h>
#include <cuda_bf16.h>
#include <cstdint>

#define B_  16
#define T_  8192
#define TP_ 512
#define E_  256
#define M_TOT (B_*TP_ + T_)     // 16384 GEMM rows: 8192 enc + 8192 pe
#define FULLMASK 0xFFFFFFFFu

// ---------------- device scratch (allocations are forbidden) ----------------
__device__ __align__(16) float     g_S [B_*TP_*E_];   // enc + enc@W_pos   (8 MB)
__device__ __align__(16) float     g_P [T_*E_];       // pe@W_pos + b_pos  (8 MB)
__device__ __align__(16) float     g_pe[T_*E_];       // sinusoid PE       (8 MB)
__device__ __align__(16) int       g_idx[B_*T_];      // aligner indices   (512 KB)
__device__ __align__(16) uint32_t  gBt [E_*E_];       // W^T in tf32 (1 MB)

// ---------------- helpers ----------------
__device__ __forceinline__ uint32_t f2tf32(float x) {
    uint32_t r;
    asm("cvt.rna.tf32.f32 %0, %1;" : "=r"(r) : "f"(x));
    return r;
}
__device__ __forceinline__ void mma_tf32(float* c, const uint32_t* a,
                                         uint32_t b0, uint32_t b1) {
    asm volatile(
        "mma.sync.aligned.m16n8k8.row.col.f32.tf32.tf32.f32 "
        "{%0,%1,%2,%3}, {%4,%5,%6,%7}, {%8,%9}, {%0,%1,%2,%3};"
        : "+f"(c[0]), "+f"(c[1]), "+f"(c[2]), "+f"(c[3])
        : "r"(a[0]), "r"(a[1]), "r"(a[2]), "r"(a[3]), "r"(b0), "r"(b1));
}

// =====================================================================
// Kernel 1 (prep):
//   blocks [0,256)   : sinusoid PE (fp32) via rotation trick
//   blocks [256,272) : parallel aligner (prefix-sum + validate, exact)
//   blocks [272,400) : W_pos transpose + tf32 convert
// =====================================================================
__global__ void __launch_bounds__(512) prep_kernel(const int* __restrict__ align_phone,
                                                   const int* __restrict__ text_phone,
                                                   const float* __restrict__ Wpos)
{
    int bid = blockIdx.x, tid = threadIdx.x;

    if (bid < 256) {
        int g  = bid * 512 + tid;                  // [0, 131072)
        int i  = g & 127;
        int t0 = (g >> 7) * 8;
        const float NEGC = -0.03597789202637730f;  // -ln(10000)/E
        float div = expf((float)(2*i) * NEGC);
        float s, c, sd, cd;
        sincosf((float)t0 * div, &s, &c);
        sincosf(div, &sd, &cd);
        float2* row = ((float2*)g_pe) + (size_t)t0*128 + i;
        #pragma unroll
        for (int r = 0; r < 8; r++) {
            row[(size_t)r*128] = make_float2(s, c);
            float s2 = fmaf(s, cd,  c*sd);
            float c2 = fmaf(c, cd, -s*sd);
            s = s2; c = c2;
        }
        return;
    }
    if (bid >= 272) {
        int idx = (bid - 272) * 512 + tid;         // [0, 65536)
        int k = idx >> 8, n = idx & 255;
        gBt[n*E_ + k] = f2tf32(Wpos[idx]);         // B[n][k] = W[k][n]
        return;
    }

    // ---------------- parallel aligner: block handles batch b ----------------
    __shared__ short stx[TP_];
    __shared__ int   wsum[16];
    __shared__ int   s_ok;
    int b = bid - 256;
    const int* arow = align_phone + (size_t)b * T_;
    int*       orow = g_idx       + (size_t)b * T_;

    for (int j = tid; j < TP_; j += 512) stx[j] = (short)text_phone[b*TP_ + j];
    if (tid == 0) s_ok = 1;
    __syncthreads();

    int base = tid * 16;
    int v[16];
    #pragma unroll
    for (int q = 0; q < 4; q++)
        *(int4*)&v[q*4] = *(const int4*)&arow[base + q*4];
    int prev = (base == 0) ? v[0] : arow[base - 1];

    unsigned cmask = 0;
    int cnt = 0;
    #pragma unroll
    for (int j = 0; j < 16; j++) {
        int c = (v[j] != prev) ? 1 : 0;
        if (base + j == 0) c = 0;
        cmask |= ((unsigned)c) << j;
        cnt += c;
        prev = v[j];
    }

    int lane = tid & 31, wId = tid >> 5;
    int incl = cnt;
    #pragma unroll
    for (int off = 1; off < 32; off <<= 1) {
        int nv = __shfl_up_sync(FULLMASK, incl, off);
        if (lane >= off) incl += nv;
    }
    if (lane == 31) wsum[wId] = incl;
    __syncthreads();
    if (tid == 0) {
        int a = 0;
        #pragma unroll
        for (int i = 0; i < 16; i++) { int t2 = wsum[i]; wsum[i] = a; a += t2; }
    }
    __syncthreads();
    int run = wsum[wId] + incl - cnt;

    bool ok = (base != 0) || (v[0] == (int)stx[0]);
    int outv[16];
    #pragma unroll
    for (int j = 0; j < 16; j++) {
        run += (int)((cmask >> j) & 1u);
        int ind = min(run, TP_ - 1);
        outv[j] = ind;
        if (base + j != 0) ok &= ((int)stx[ind] == v[j]);
    }
    #pragma unroll
    for (int q = 0; q < 4; q++)
        *(int4*)&orow[base + q*4] = *(const int4*)&outv[q*4];

    if (!ok) atomicAnd(&s_ok, 0);
    __syncthreads();
    if (s_ok == 0 && tid == 0) {
        int ind = 0, before = (int)stx[0];
        orow[0] = 0;
        for (int t = 1; t < T_; t++) {
            int a = arow[t];
            if (a != before) { ind = min(ind + 1, TP_ - 1); before = (int)stx[ind]; }
            orow[t] = ind;
        }
    }
}

// =====================================================================
// Kernel 2: single-pass tf32 tensor-core GEMM (mma.m16n8k8.tf32).
// CTA tile 128(M) x 256(N), grid 128 (one wave), 512 threads = 16 warps
// of 32x64. K=256 in 8 slices of 32, double-buffered smem, row stride
// 36 words -> conflict-free LDS.32 fragment loads. A cvt.rna in-load.
// =====================================================================
#define ASTR 36
#define BSTR 36
#define A_WORDS (128*ASTR)            // 4608 words = 18 KB
#define B_WORDS (256*BSTR)            // 9216 words = 36 KB
#define BUF_WORDS (A_WORDS + B_WORDS) // 13824 words = 54 KB
#define SMEM_GEMM (2*BUF_WORDS*4)     // 110592 bytes

__global__ void __launch_bounds__(512, 1) gemm_kernel(const float* __restrict__ enc,
                                                      const float* __restrict__ bpos)
{
    extern __shared__ __align__(16) uint32_t smw[];

    int tid  = threadIdx.x;
    int wid  = tid >> 5, lid = tid & 31;
    int wm   = wid & 3;            // 4 m-warps of 32 rows
    int wn   = wid >> 2;           // 4 n-warps of 64 cols
    int g    = lid >> 2, tig = lid & 3;
    int mBase = blockIdx.x * 128;
    bool isEnc = (mBase < B_*TP_);
    const float4* Afp = isEnc ? (const float4*)(enc + (size_t)mBase*E_)
                              : (const float4*)(g_pe + (size_t)(mBase - B_*TP_)*E_);

    float acc[2][8][4];
    #pragma unroll
    for (int t = 0; t < 2; t++)
        #pragma unroll
        for (int u = 0; u < 8; u++)
            #pragma unroll
            for (int q = 0; q < 4; q++) acc[t][u][q] = 0.f;

    auto load_slice = [&](int kc, int bsel) {
        uint32_t* As = smw + bsel*BUF_WORDS;
        uint32_t* Bs = As + A_WORDS;
        #pragma unroll
        for (int i = 0; i < 2; i++) {            // A: 128 rows x 8 float4
            int idx = tid + i*512;
            int row = idx >> 3, c4 = idx & 7;
            float4 v = Afp[(size_t)row*64 + kc*8 + c4];
            uint4 w = make_uint4(f2tf32(v.x), f2tf32(v.y), f2tf32(v.z), f2tf32(v.w));
            *(uint4*)&As[row*ASTR + c4*4] = w;
        }
        #pragma unroll
        for (int i = 0; i < 4; i++) {            // B: 256 rows x 8 uint4 (tf32)
            int idx = tid + i*512;
            int row = idx >> 3, c4 = idx & 7;
            uint4 w = ((const uint4*)gBt)[(size_t)row*64 + kc*8 + c4];
            *(uint4*)&Bs[row*BSTR + c4*4] = w;
        }
    };

    load_slice(0, 0);
    __syncthreads();

    for (int kc = 0; kc < 8; kc++) {
        if (kc + 1 < 8) load_slice(kc + 1, (kc + 1) & 1);

        const uint32_t* As = smw + (kc & 1)*BUF_WORDS;
        const uint32_t* Bs = As + A_WORDS;

        #pragma unroll
        for (int k8 = 0; k8 < 4; k8++) {
            int c0 = k8*8 + tig;                 // A col / B k-row
            uint32_t a[2][4];
            #pragma unroll
            for (int t = 0; t < 2; t++) {        // A fragments (m16k8 x2)
                int r0 = wm*32 + t*16 + g;
                a[t][0] = As[(r0    )*ASTR + c0    ];
                a[t][1] = As[(r0 + 8)*ASTR + c0    ];
                a[t][2] = As[(r0    )*ASTR + c0 + 4];
                a[t][3] = As[(r0 + 8)*ASTR + c0 + 4];
            }
            #pragma unroll
            for (int u = 0; u < 8; u++) {        // B fragments (k8n8), 2 mma each
                int n0 = wn*64 + u*8 + g;
                uint32_t b0 = Bs[n0*BSTR + c0    ];
                uint32_t b1 = Bs[n0*BSTR + c0 + 4];
                mma_tf32(acc[0][u], a[0], b0, b1);
                mma_tf32(acc[1][u], a[1], b0, b1);
            }
        }
        __syncthreads();
    }

    // ---- epilogue ----
    #pragma unroll
    for (int t = 0; t < 2; t++) {
        int rm = mBase + wm*32 + t*16 + g;
        #pragma unroll
        for (int u = 0; u < 8; u++) {
            int n  = wn*64 + u*8 + tig*2;
            int i0 = rm*128 + (n >> 1);          // float2 index, row rm
            int i1 = i0 + 8*128;                 // row rm+8
            if (isEnc) {
                float2 e0 = ((const float2*)enc)[i0];
                float2 e1 = ((const float2*)enc)[i1];
                ((float2*)g_S)[i0] = make_float2(acc[t][u][0] + e0.x,
                                                 acc[t][u][1] + e0.y);
                ((float2*)g_S)[i1] = make_float2(acc[t][u][2] + e1.x,
                                                 acc[t][u][3] + e1.y);
            } else {
                float2 bp = ((const float2*)bpos)[n >> 1];
                int j0 = i0 - B_*TP_*128;
                ((float2*)g_P)[j0]         = make_float2(acc[t][u][0] + bp.x,
                                                         acc[t][u][1] + bp.y);
                ((float2*)g_P)[j0 + 8*128] = make_float2(acc[t][u][2] + bp.x,
                                                         acc[t][u][3] + bp.y);
            }
        }
    }
}

// =====================================================================
// Kernel 3: chunk-reuse assemble.
// =====================================================================
__global__ void __launch_bounds__(256) main_kernel(const float* __restrict__ pitch,
                                                   const int*   __restrict__ beats,
                                                   const float* __restrict__ Wpitch,
                                                   const float* __restrict__ bpitch,
                                                   const float* __restrict__ embBeats,
                                                   float* __restrict__ out)
{
    __shared__ __align__(16) float sP[16*E_];     // 16 KB = 1024 float4
    __shared__ int   sidx  [256];
    __shared__ float spitch[256];
    __shared__ int   sbeats[256];

    int tid = threadIdx.x;
    int t0  = blockIdx.x * 16;
    int e4  = tid & 63;
    int rp  = tid >> 6;

    #pragma unroll
    for (int i = 0; i < 4; i++)
        ((float4*)sP)[tid + i*256] = ((const float4*)g_P)[(size_t)t0*64 + tid + i*256];
    {
        int b = tid >> 4, tt = tid & 15;
        int bt = b*T_ + t0 + tt;
        sidx[tid]   = g_idx[bt];
        spitch[tid] = pitch[bt];
        sbeats[tid] = beats[bt];
    }
    __syncthreads();

    float4 wp  = ((const float4*)Wpitch)[e4];
    float4 bp  = ((const float4*)bpitch)[e4];
    float4 eb0 = ((const float4*)embBeats)[e4];
    float4 eb1 = ((const float4*)embBeats)[64 + e4];

    #pragma unroll 4
    for (int i = 0; i < 64; i++) {
        int p  = i*4 + rp;
        int b  = p >> 4, tt = p & 15;
        int ix = sidx[p];
        float4 s  = *(const float4*)&g_S[((size_t)(b*TP_ + ix))*E_ + e4*4];
        float4 pr = ((const float4*)sP)[tt*64 + e4];
        float  pv = spitch[p];
        float4 ev = sbeats[p] ? eb1 : eb0;
        float4 o;
        o.x = s.x + pr.x + fmaf(pv, wp.x, bp.x) + ev.x;
        o.y = s.y + pr.y + fmaf(pv, wp.y, bp.y) + ev.y;
        o.z = s.z + pr.z + fmaf(pv, wp.z, bp.z) + ev.z;
        o.w = s.w + pr.w + fmaf(pv, wp.w, bp.w) + ev.w;
        ((float4*)out)[((size_t)b*T_ + t0 + tt)*64 + e4] = o;
    }
}

// =====================================================================
extern "C" void kernel_launch(void* const* d_in, const int* in_sizes, int n_in,
                              void* d_out, int out_size)
{
    const float* enc      = (const float*)d_in[0];
    const int*   align_p  = (const int*)  d_in[1];
    const int*   text_p   = (const int*)  d_in[2];
    const float* pitch    = (const float*)d_in[3];
    const int*   beats    = (const int*)  d_in[4];
    const float* W_pitch  = (const float*)d_in[5];
    const float* b_pitch  = (const float*)d_in[6];
    const float* W_pos    = (const float*)d_in[7];
    const float* b_pos    = (const float*)d_in[8];
    const float* emb_b    = (const float*)d_in[9];
    float* out = (float*)d_out;

    static int smem_set = 0;
    if (!smem_set) {
        cudaFuncSetAttribute(gemm_kernel,
                             cudaFuncAttributeMaxDynamicSharedMemorySize, SMEM_GEMM);
        smem_set = 1;
    }

    prep_kernel<<<400, 512>>>(align_p, text_p, W_pos);

    gemm_kernel<<<M_TOT/128, 512, SMEM_GEMM>>>(enc, b_pos);

    main_kernel<<<T_/16, 256>>>(pitch, beats, W_pitch, b_pitch, emb_b, out);
}

// round 13
// speedup vs baseline: 1.3573x; 1.1666x over previous
#include <cuda_runtime.h>
#include <cuda_fp16.h>
#include <cstdint>

#define B_  16
#define T_  8192
#define TP_ 512
#define E_  256
#define M_TOT (B_*TP_ + T_)     // 16384 GEMM rows: 8192 enc + 8192 pe
#define FULLMASK 0xFFFFFFFFu

// ---------------- device scratch (allocations are forbidden) ----------------
__device__ __align__(16) float   g_S [B_*TP_*E_];   // enc + enc@W_pos   (8 MB)
__device__ __align__(16) float   g_P [T_*E_];       // pe@W_pos + b_pos  (8 MB)
__device__ __align__(16) float   g_pe[T_*E_];       // sinusoid PE       (8 MB)
__device__ __align__(16) int     g_idx[B_*T_];      // aligner indices   (512 KB)
__device__ __align__(16) __half  gBh [E_*E_];       // W^T in fp16 (128 KB)

// ---------------- helpers ----------------
// SW64 swizzle: 64-byte rows, XOR bits [5:4] with bits [8:7]
#define SWZ64(x) ((x) ^ (((x) >> 3) & 0x30))

__device__ __forceinline__ void ldsm_x4(uint32_t& r0, uint32_t& r1, uint32_t& r2,
                                        uint32_t& r3, uint32_t addr) {
    asm volatile("ldmatrix.sync.aligned.m8n8.x4.shared.b16 {%0,%1,%2,%3}, [%4];"
                 : "=r"(r0), "=r"(r1), "=r"(r2), "=r"(r3) : "r"(addr));
}
__device__ __forceinline__ uint32_t smem_u32(const void* p) {
    uint32_t a;
    asm("{ .reg .u64 t; cvta.to.shared.u64 t, %1; cvt.u32.u64 %0, t; }" : "=r"(a) : "l"(p));
    return a;
}
__device__ __forceinline__ void mma_f16(float* c, const uint32_t* a,
                                        uint32_t b0, uint32_t b1) {
    asm volatile(
        "mma.sync.aligned.m16n8k16.row.col.f32.f16.f16.f32 "
        "{%0,%1,%2,%3}, {%4,%5,%6,%7}, {%8,%9}, {%0,%1,%2,%3};"
        : "+f"(c[0]), "+f"(c[1]), "+f"(c[2]), "+f"(c[3])
        : "r"(a[0]), "r"(a[1]), "r"(a[2]), "r"(a[3]), "r"(b0), "r"(b1));
}
__device__ __forceinline__ uint32_t pack_h2(float a, float b) {
    __half2 h = __floats2half2_rn(a, b);
    return *reinterpret_cast<uint32_t*>(&h);
}

// =====================================================================
// Kernel 1 (prep):
//   blocks [0,256)   : sinusoid PE (fp32) via rotation trick
//   blocks [256,272) : parallel aligner (prefix-sum + validate, exact)
//   blocks [272,400) : W_pos transpose + fp16 convert
// =====================================================================
__global__ void __launch_bounds__(512) prep_kernel(const int* __restrict__ align_phone,
                                                   const int* __restrict__ text_phone,
                                                   const float* __restrict__ Wpos)
{
    int bid = blockIdx.x, tid = threadIdx.x;

    if (bid < 256) {
        int g  = bid * 512 + tid;                  // [0, 131072)
        int i  = g & 127;
        int t0 = (g >> 7) * 8;
        const float NEGC = -0.03597789202637730f;  // -ln(10000)/E
        float div = expf((float)(2*i) * NEGC);
        float s, c, sd, cd;
        sincosf((float)t0 * div, &s, &c);
        sincosf(div, &sd, &cd);
        float2* row = ((float2*)g_pe) + (size_t)t0*128 + i;
        #pragma unroll
        for (int r = 0; r < 8; r++) {
            row[(size_t)r*128] = make_float2(s, c);
            float s2 = fmaf(s, cd,  c*sd);
            float c2 = fmaf(c, cd, -s*sd);
            s = s2; c = c2;
        }
        return;
    }
    if (bid >= 272) {
        int idx = (bid - 272) * 512 + tid;         // [0, 65536)
        int k = idx >> 8, n = idx & 255;
        gBh[n*E_ + k] = __float2half_rn(Wpos[idx]);  // B[n][k] = W[k][n]
        return;
    }

    // ---------------- parallel aligner: block handles batch b ----------------
    __shared__ short stx[TP_];
    __shared__ int   wsum[16];
    __shared__ int   s_ok;
    int b = bid - 256;
    const int* arow = align_phone + (size_t)b * T_;
    int*       orow = g_idx       + (size_t)b * T_;

    for (int j = tid; j < TP_; j += 512) stx[j] = (short)text_phone[b*TP_ + j];
    if (tid == 0) s_ok = 1;
    __syncthreads();

    int base = tid * 16;
    int v[16];
    #pragma unroll
    for (int q = 0; q < 4; q++)
        *(int4*)&v[q*4] = *(const int4*)&arow[base + q*4];
    int prev = (base == 0) ? v[0] : arow[base - 1];

    unsigned cmask = 0;
    int cnt = 0;
    #pragma unroll
    for (int j = 0; j < 16; j++) {
        int c = (v[j] != prev) ? 1 : 0;
        if (base + j == 0) c = 0;
        cmask |= ((unsigned)c) << j;
        cnt += c;
        prev = v[j];
    }

    int lane = tid & 31, wId = tid >> 5;
    int incl = cnt;
    #pragma unroll
    for (int off = 1; off < 32; off <<= 1) {
        int nv = __shfl_up_sync(FULLMASK, incl, off);
        if (lane >= off) incl += nv;
    }
    if (lane == 31) wsum[wId] = incl;
    __syncthreads();
    if (tid == 0) {
        int a = 0;
        #pragma unroll
        for (int i = 0; i < 16; i++) { int t2 = wsum[i]; wsum[i] = a; a += t2; }
    }
    __syncthreads();
    int run = wsum[wId] + incl - cnt;

    bool ok = (base != 0) || (v[0] == (int)stx[0]);
    int outv[16];
    #pragma unroll
    for (int j = 0; j < 16; j++) {
        run += (int)((cmask >> j) & 1u);
        int ind = min(run, TP_ - 1);
        outv[j] = ind;
        if (base + j != 0) ok &= ((int)stx[ind] == v[j]);
    }
    #pragma unroll
    for (int q = 0; q < 4; q++)
        *(int4*)&orow[base + q*4] = *(const int4*)&outv[q*4];

    if (!ok) atomicAnd(&s_ok, 0);
    __syncthreads();
    if (s_ok == 0 && tid == 0) {
        int ind = 0, before = (int)stx[0];
        orow[0] = 0;
        for (int t = 1; t < T_; t++) {
            int a = arow[t];
            if (a != before) { ind = min(ind + 1, TP_ - 1); before = (int)stx[ind]; }
            orow[t] = ind;
        }
    }
}

// =====================================================================
// Kernel 2: single-pass fp16 tensor-core GEMM (mma.m16n8k16.f16, f32 acc).
// fp16 mantissa (10+1 bits) == tf32 precision, but K=16 per mma -> half
// the mma instructions of R12 (4096/CTA). CTA tile 128x256, grid 128
// (one wave), 512 threads = 16 warps of 32x64. K=256 in 8 slices of 32,
// double-buffered 48 KB static smem, SW64 swizzle + ldmatrix.
// =====================================================================
#define A_OFF 0
#define B_OFF 8192                  // A: 128 rows x 64B = 8 KB
#define BUFSZ 24576                 // + B: 256 rows x 64B = 16 KB
                                    // 2 buffers = 48 KB static

__global__ void __launch_bounds__(512, 1) gemm_kernel(const float* __restrict__ enc,
                                                      const float* __restrict__ bpos)
{
    __shared__ __align__(128) char smem[2*BUFSZ];
    uint32_t sb = smem_u32(smem);

    int tid  = threadIdx.x;
    int wid  = tid >> 5, lid = tid & 31;
    int wm   = wid & 3;            // 4 m-warps of 32 rows
    int wn   = wid >> 2;           // 4 n-warps of 64 cols
    int g    = lid >> 2, tig = lid & 3;
    int mBase = blockIdx.x * 128;
    bool isEnc = (mBase < B_*TP_);
    const float4* Afp = isEnc ? (const float4*)(enc + (size_t)mBase*E_)
                              : (const float4*)(g_pe + (size_t)(mBase - B_*TP_)*E_);

    float acc[2][8][4];
    #pragma unroll
    for (int t = 0; t < 2; t++)
        #pragma unroll
        for (int u = 0; u < 8; u++)
            #pragma unroll
            for (int q = 0; q < 4; q++) acc[t][u][q] = 0.f;

    auto load_slice = [&](int kc, int bsel) {
        char* buf = smem + bsel*BUFSZ;
        #pragma unroll
        for (int i = 0; i < 2; i++) {            // A: 128 rows x 8 float4 -> fp16
            int idx = tid + i*512;
            int row = idx >> 3, c4 = idx & 7;
            float4 v = Afp[(size_t)row*64 + kc*8 + c4];
            uint2 h;
            h.x = pack_h2(v.x, v.y);
            h.y = pack_h2(v.z, v.w);
            uint32_t off = SWZ64((uint32_t)(row*64 + c4*8));
            *(uint2*)(buf + A_OFF + off) = h;
        }
        #pragma unroll
        for (int i = 0; i < 2; i++) {            // B: 256 rows x 4 uint4 (fp16)
            int idx = tid + i*512;
            int row = idx >> 2, c8 = idx & 3;
            uint4 w = ((const uint4*)gBh)[(size_t)row*32 + kc*4 + c8];
            uint32_t off = SWZ64((uint32_t)(row*64 + c8*16));
            *(uint4*)(buf + B_OFF + off) = w;
        }
    };

    load_slice(0, 0);
    __syncthreads();

    for (int kc = 0; kc < 8; kc++) {
        if (kc + 1 < 8) load_slice(kc + 1, (kc + 1) & 1);

        uint32_t ab = sb + (kc & 1)*BUFSZ;
        #pragma unroll
        for (int ks = 0; ks < 2; ks++) {
            uint32_t ah[2][4], bh[8][2];
            #pragma unroll
            for (int t = 0; t < 2; t++) {        // A fragments (m16k16 x2)
                uint32_t off = (uint32_t)((wm*32 + t*16 + (lid & 15))*64
                                          + ks*32 + ((lid >> 4) & 1)*16);
                ldsm_x4(ah[t][0], ah[t][1], ah[t][2], ah[t][3],
                        ab + A_OFF + SWZ64(off));
            }
            #pragma unroll
            for (int up = 0; up < 4; up++) {     // B fragments (64 cols)
                uint32_t off = (uint32_t)((wn*64 + up*16 + ((lid >> 4) & 1)*8
                                           + (lid & 7))*64
                                          + ks*32 + ((lid >> 3) & 1)*16);
                ldsm_x4(bh[2*up][0], bh[2*up][1], bh[2*up+1][0], bh[2*up+1][1],
                        ab + B_OFF + SWZ64(off));
            }
            #pragma unroll
            for (int t = 0; t < 2; t++)
                #pragma unroll
                for (int u = 0; u < 8; u++)
                    mma_f16(acc[t][u], ah[t], bh[u][0], bh[u][1]);
        }
        __syncthreads();
    }

    // ---- epilogue ----
    #pragma unroll
    for (int t = 0; t < 2; t++) {
        int rm = mBase + wm*32 + t*16 + g;
        #pragma unroll
        for (int u = 0; u < 8; u++) {
            int n  = wn*64 + u*8 + tig*2;
            int i0 = rm*128 + (n >> 1);          // float2 index, row rm
            int i1 = i0 + 8*128;                 // row rm+8
            if (isEnc) {
                float2 e0 = ((const float2*)enc)[i0];
                float2 e1 = ((const float2*)enc)[i1];
                ((float2*)g_S)[i0] = make_float2(acc[t][u][0] + e0.x,
                                                 acc[t][u][1] + e0.y);
                ((float2*)g_S)[i1] = make_float2(acc[t][u][2] + e1.x,
                                                 acc[t][u][3] + e1.y);
            } else {
                float2 bp = ((const float2*)bpos)[n >> 1];
                int j0 = i0 - B_*TP_*128;
                ((float2*)g_P)[j0]         = make_float2(acc[t][u][0] + bp.x,
                                                         acc[t][u][1] + bp.y);
                ((float2*)g_P)[j0 + 8*128] = make_float2(acc[t][u][2] + bp.x,
                                                         acc[t][u][3] + bp.y);
            }
        }
    }
}

// =====================================================================
// Kernel 3: chunk-reuse assemble.
// =====================================================================
__global__ void __launch_bounds__(256) main_kernel(const float* __restrict__ pitch,
                                                   const int*   __restrict__ beats,
                                                   const float* __restrict__ Wpitch,
                                                   const float* __restrict__ bpitch,
                                                   const float* __restrict__ embBeats,
                                                   float* __restrict__ out)
{
    __shared__ __align__(16) float sP[16*E_];     // 16 KB = 1024 float4
    __shared__ int   sidx  [256];
    __shared__ float spitch[256];
    __shared__ int   sbeats[256];

    int tid = threadIdx.x;
    int t0  = blockIdx.x * 16;
    int e4  = tid & 63;
    int rp  = tid >> 6;

    #pragma unroll
    for (int i = 0; i < 4; i++)
        ((float4*)sP)[tid + i*256] = ((const float4*)g_P)[(size_t)t0*64 + tid + i*256];
    {
        int b = tid >> 4, tt = tid & 15;
        int bt = b*T_ + t0 + tt;
        sidx[tid]   = g_idx[bt];
        spitch[tid] = pitch[bt];
        sbeats[tid] = beats[bt];
    }
    __syncthreads();

    float4 wp  = ((const float4*)Wpitch)[e4];
    float4 bp  = ((const float4*)bpitch)[e4];
    float4 eb0 = ((const float4*)embBeats)[e4];
    float4 eb1 = ((const float4*)embBeats)[64 + e4];

    #pragma unroll 4
    for (int i = 0; i < 64; i++) {
        int p  = i*4 + rp;
        int b  = p >> 4, tt = p & 15;
        int ix = sidx[p];
        float4 s  = *(const float4*)&g_S[((size_t)(b*TP_ + ix))*E_ + e4*4];
        float4 pr = ((const float4*)sP)[tt*64 + e4];
        float  pv = spitch[p];
        float4 ev = sbeats[p] ? eb1 : eb0;
        float4 o;
        o.x = s.x + pr.x + fmaf(pv, wp.x, bp.x) + ev.x;
        o.y = s.y + pr.y + fmaf(pv, wp.y, bp.y) + ev.y;
        o.z = s.z + pr.z + fmaf(pv, wp.z, bp.z) + ev.z;
        o.w = s.w + pr.w + fmaf(pv, wp.w, bp.w) + ev.w;
        ((float4*)out)[((size_t)b*T_ + t0 + tt)*64 + e4] = o;
    }
}

// =====================================================================
extern "C" void kernel_launch(void* const* d_in, const int* in_sizes, int n_in,
                              void* d_out, int out_size)
{
    const float* enc      = (const float*)d_in[0];
    const int*   align_p  = (const int*)  d_in[1];
    const int*   text_p   = (const int*)  d_in[2];
    const float* pitch    = (const float*)d_in[3];
    const int*   beats    = (const int*)  d_in[4];
    const float* W_pitch  = (const float*)d_in[5];
    const float* b_pitch  = (const float*)d_in[6];
    const float* W_pos    = (const float*)d_in[7];
    const float* b_pos    = (const float*)d_in[8];
    const float* emb_b    = (const float*)d_in[9];
    float* out = (float*)d_out;

    prep_kernel<<<400, 512>>>(align_p, text_p, W_pos);

    gemm_kernel<<<M_TOT/128, 512>>>(enc, b_pos);

    main_kernel<<<T_/16, 256>>>(pitch, beats, W_pitch, b_pitch, emb_b, out);
}

// round 14
// speedup vs baseline: 1.3891x; 1.0234x over previous
#include <cuda_runtime.h>
#include <cuda_fp16.h>
#include <cstdint>

#define B_  16
#define T_  8192
#define TP_ 512
#define E_  256
#define M_TOT (B_*TP_ + T_)     // 16384 GEMM rows: 8192 enc + 8192 pe
#define FULLMASK 0xFFFFFFFFu

// ---------------- device scratch (allocations are forbidden) ----------------
__device__ __align__(16) float   g_S [B_*TP_*E_];   // enc + enc@W_pos   (8 MB)
__device__ __align__(16) float   g_P [T_*E_];       // pe@W_pos + b_pos  (8 MB)
__device__ __align__(16) float   g_pe[T_*E_];       // sinusoid PE       (8 MB)
__device__ __align__(16) int     g_idx[B_*T_];      // aligner indices   (512 KB)
__device__ __align__(16) __half  gBh [E_*E_];       // W^T in fp16 (128 KB)

// ---------------- helpers ----------------
// SW64 swizzle: 64-byte rows, XOR bits [5:4] with bits [8:7]
#define SWZ64(x) ((x) ^ (((x) >> 3) & 0x30))

__device__ __forceinline__ void ldsm_x4(uint32_t& r0, uint32_t& r1, uint32_t& r2,
                                        uint32_t& r3, uint32_t addr) {
    asm volatile("ldmatrix.sync.aligned.m8n8.x4.shared.b16 {%0,%1,%2,%3}, [%4];"
                 : "=r"(r0), "=r"(r1), "=r"(r2), "=r"(r3) : "r"(addr));
}
__device__ __forceinline__ uint32_t smem_u32(const void* p) {
    uint32_t a;
    asm("{ .reg .u64 t; cvta.to.shared.u64 t, %1; cvt.u32.u64 %0, t; }" : "=r"(a) : "l"(p));
    return a;
}
__device__ __forceinline__ void mma_f16(float* c, const uint32_t* a,
                                        uint32_t b0, uint32_t b1) {
    asm volatile(
        "mma.sync.aligned.m16n8k16.row.col.f32.f16.f16.f32 "
        "{%0,%1,%2,%3}, {%4,%5,%6,%7}, {%8,%9}, {%0,%1,%2,%3};"
        : "+f"(c[0]), "+f"(c[1]), "+f"(c[2]), "+f"(c[3])
        : "r"(a[0]), "r"(a[1]), "r"(a[2]), "r"(a[3]), "r"(b0), "r"(b1));
}
__device__ __forceinline__ uint32_t pack_h2(float a, float b) {
    __half2 h = __floats2half2_rn(a, b);
    return *reinterpret_cast<uint32_t*>(&h);
}

// =====================================================================
// Kernel 1 (prep):
//   blocks [0,256)   : sinusoid PE (fp32) via rotation trick
//   blocks [256,272) : parallel aligner (prefix-sum + validate, exact)
//   blocks [272,400) : W_pos transpose + fp16 convert
// =====================================================================
__global__ void __launch_bounds__(512) prep_kernel(const int* __restrict__ align_phone,
                                                   const int* __restrict__ text_phone,
                                                   const float* __restrict__ Wpos)
{
    int bid = blockIdx.x, tid = threadIdx.x;

    if (bid < 256) {
        int g  = bid * 512 + tid;                  // [0, 131072)
        int i  = g & 127;
        int t0 = (g >> 7) * 8;
        const float NEGC = -0.03597789202637730f;  // -ln(10000)/E
        float div = expf((float)(2*i) * NEGC);
        float s, c, sd, cd;
        sincosf((float)t0 * div, &s, &c);
        sincosf(div, &sd, &cd);
        float2* row = ((float2*)g_pe) + (size_t)t0*128 + i;
        #pragma unroll
        for (int r = 0; r < 8; r++) {
            row[(size_t)r*128] = make_float2(s, c);
            float s2 = fmaf(s, cd,  c*sd);
            float c2 = fmaf(c, cd, -s*sd);
            s = s2; c = c2;
        }
        return;
    }
    if (bid >= 272) {
        int idx = (bid - 272) * 512 + tid;         // [0, 65536)
        int k = idx >> 8, n = idx & 255;
        gBh[n*E_ + k] = __float2half_rn(Wpos[idx]);  // B[n][k] = W[k][n]
        return;
    }

    // ---------------- parallel aligner: block handles batch b ----------------
    __shared__ short stx[TP_];
    __shared__ int   wsum[16];
    __shared__ int   s_ok;
    int b = bid - 256;
    const int* arow = align_phone + (size_t)b * T_;
    int*       orow = g_idx       + (size_t)b * T_;

    for (int j = tid; j < TP_; j += 512) stx[j] = (short)text_phone[b*TP_ + j];
    if (tid == 0) s_ok = 1;
    __syncthreads();

    int base = tid * 16;
    int v[16];
    #pragma unroll
    for (int q = 0; q < 4; q++)
        *(int4*)&v[q*4] = *(const int4*)&arow[base + q*4];
    int prev = (base == 0) ? v[0] : arow[base - 1];

    unsigned cmask = 0;
    int cnt = 0;
    #pragma unroll
    for (int j = 0; j < 16; j++) {
        int c = (v[j] != prev) ? 1 : 0;
        if (base + j == 0) c = 0;
        cmask |= ((unsigned)c) << j;
        cnt += c;
        prev = v[j];
    }

    int lane = tid & 31, wId = tid >> 5;
    int incl = cnt;
    #pragma unroll
    for (int off = 1; off < 32; off <<= 1) {
        int nv = __shfl_up_sync(FULLMASK, incl, off);
        if (lane >= off) incl += nv;
    }
    if (lane == 31) wsum[wId] = incl;
    __syncthreads();
    if (tid == 0) {
        int a = 0;
        #pragma unroll
        for (int i = 0; i < 16; i++) { int t2 = wsum[i]; wsum[i] = a; a += t2; }
    }
    __syncthreads();
    int run = wsum[wId] + incl - cnt;

    bool ok = (base != 0) || (v[0] == (int)stx[0]);
    int outv[16];
    #pragma unroll
    for (int j = 0; j < 16; j++) {
        run += (int)((cmask >> j) & 1u);
        int ind = min(run, TP_ - 1);
        outv[j] = ind;
        if (base + j != 0) ok &= ((int)stx[ind] == v[j]);
    }
    #pragma unroll
    for (int q = 0; q < 4; q++)
        *(int4*)&orow[base + q*4] = *(const int4*)&outv[q*4];

    if (!ok) atomicAnd(&s_ok, 0);
    __syncthreads();
    if (s_ok == 0 && tid == 0) {
        int ind = 0, before = (int)stx[0];
        orow[0] = 0;
        for (int t = 1; t < T_; t++) {
            int a = arow[t];
            if (a != before) { ind = min(ind + 1, TP_ - 1); before = (int)stx[ind]; }
            orow[t] = ind;
        }
    }
}

// =====================================================================
// Kernel 2: single-pass fp16 GEMM (mma.m16n8k16.f16, f32 acc), software
// pipelined: A staged via registers (LDG before mma, STS after — latency
// hidden behind mma), B streamed via cp.async straight into swizzled
// smem. CTA tile 128x256, grid 128 (one wave), 16 warps of 32x64,
// K=256 in 8 slices of 32, double-buffered 48 KB static smem.
// =====================================================================
#define A_OFF 0
#define B_OFF 8192                  // A: 128 rows x 64B = 8 KB
#define BUFSZ 24576                 // + B: 256 rows x 64B = 16 KB

__global__ void __launch_bounds__(512, 1) gemm_kernel(const float* __restrict__ enc,
                                                      const float* __restrict__ bpos)
{
    __shared__ __align__(128) char smem[2*BUFSZ];
    uint32_t sb = smem_u32(smem);

    int tid  = threadIdx.x;
    int wid  = tid >> 5, lid = tid & 31;
    int wm   = wid & 3;            // 4 m-warps of 32 rows
    int wn   = wid >> 2;           // 4 n-warps of 64 cols
    int g    = lid >> 2, tig = lid & 3;
    int mBase = blockIdx.x * 128;
    bool isEnc = (mBase < B_*TP_);
    const float4* Afp = isEnc ? (const float4*)(enc + (size_t)mBase*E_)
                              : (const float4*)(g_pe + (size_t)(mBase - B_*TP_)*E_);

    // per-thread fixed load/store coordinates
    int arow0 = tid >> 3,         ac4 = tid & 7;          // A elem 0
    int arow1 = (tid + 512) >> 3;                          // A elem 1 (same c4)
    uint32_t asw0 = SWZ64((uint32_t)(arow0*64 + ac4*8));
    uint32_t asw1 = SWZ64((uint32_t)(arow1*64 + ac4*8));
    int brow0 = tid >> 2,         bc8 = tid & 3;          // B elem 0
    int brow1 = (tid + 512) >> 2;
    uint32_t bsw0 = SWZ64((uint32_t)(brow0*64 + bc8*16));
    uint32_t bsw1 = SWZ64((uint32_t)(brow1*64 + bc8*16));

    float acc[2][8][4];
    #pragma unroll
    for (int t = 0; t < 2; t++)
        #pragma unroll
        for (int u = 0; u < 8; u++)
            #pragma unroll
            for (int q = 0; q < 4; q++) acc[t][u][q] = 0.f;

    float4 aR0, aR1;
    auto lda = [&](int kc) {
        aR0 = Afp[(size_t)arow0*64 + kc*8 + ac4];
        aR1 = Afp[(size_t)arow1*64 + kc*8 + ac4];
    };
    auto sta = [&](char* buf) {
        uint2 h0, h1;
        h0.x = pack_h2(aR0.x, aR0.y);  h0.y = pack_h2(aR0.z, aR0.w);
        h1.x = pack_h2(aR1.x, aR1.y);  h1.y = pack_h2(aR1.z, aR1.w);
        *(uint2*)(buf + A_OFF + asw0) = h0;
        *(uint2*)(buf + A_OFF + asw1) = h1;
    };
    auto ldb_async = [&](int kc, uint32_t bufaddr) {
        const uint4* s0 = &((const uint4*)gBh)[(size_t)brow0*32 + kc*4 + bc8];
        const uint4* s1 = &((const uint4*)gBh)[(size_t)brow1*32 + kc*4 + bc8];
        asm volatile("cp.async.cg.shared.global [%0], [%1], 16;"
                     :: "r"(bufaddr + B_OFF + bsw0), "l"(s0) : "memory");
        asm volatile("cp.async.cg.shared.global [%0], [%1], 16;"
                     :: "r"(bufaddr + B_OFF + bsw1), "l"(s1) : "memory");
    };

    // prologue: slice 0
    lda(0);
    ldb_async(0, sb);
    asm volatile("cp.async.commit_group;" ::: "memory");
    sta(smem);
    asm volatile("cp.async.wait_group 0;" ::: "memory");
    __syncthreads();

    for (int kc = 0; kc < 8; kc++) {
        if (kc < 7) {                            // issue next-slice loads early
            lda(kc + 1);
            ldb_async(kc + 1, sb + ((kc + 1) & 1)*BUFSZ);
            asm volatile("cp.async.commit_group;" ::: "memory");
        }

        uint32_t ab = sb + (kc & 1)*BUFSZ;       // mma phase (hides latencies)
        #pragma unroll
        for (int ks = 0; ks < 2; ks++) {
            uint32_t ah[2][4], bh[8][2];
            #pragma unroll
            for (int t = 0; t < 2; t++) {
                uint32_t off = (uint32_t)((wm*32 + t*16 + (lid & 15))*64
                                          + ks*32 + ((lid >> 4) & 1)*16);
                ldsm_x4(ah[t][0], ah[t][1], ah[t][2], ah[t][3],
                        ab + A_OFF + SWZ64(off));
            }
            #pragma unroll
            for (int up = 0; up < 4; up++) {
                uint32_t off = (uint32_t)((wn*64 + up*16 + ((lid >> 4) & 1)*8
                                           + (lid & 7))*64
                                          + ks*32 + ((lid >> 3) & 1)*16);
                ldsm_x4(bh[2*up][0], bh[2*up][1], bh[2*up+1][0], bh[2*up+1][1],
                        ab + B_OFF + SWZ64(off));
            }
            #pragma unroll
            for (int t = 0; t < 2; t++)
                #pragma unroll
                for (int u = 0; u < 8; u++)
                    mma_f16(acc[t][u], ah[t], bh[u][0], bh[u][1]);
        }

        if (kc < 7) {                            // data arrived during mma
            sta(smem + ((kc + 1) & 1)*BUFSZ);
            asm volatile("cp.async.wait_group 0;" ::: "memory");
        }
        __syncthreads();
    }

    // ---- epilogue ----
    #pragma unroll
    for (int t = 0; t < 2; t++) {
        int rm = mBase + wm*32 + t*16 + g;
        #pragma unroll
        for (int u = 0; u < 8; u++) {
            int n  = wn*64 + u*8 + tig*2;
            int i0 = rm*128 + (n >> 1);          // float2 index, row rm
            int i1 = i0 + 8*128;                 // row rm+8
            if (isEnc) {
                float2 e0 = ((const float2*)enc)[i0];
                float2 e1 = ((const float2*)enc)[i1];
                ((float2*)g_S)[i0] = make_float2(acc[t][u][0] + e0.x,
                                                 acc[t][u][1] + e0.y);
                ((float2*)g_S)[i1] = make_float2(acc[t][u][2] + e1.x,
                                                 acc[t][u][3] + e1.y);
            } else {
                float2 bp = ((const float2*)bpos)[n >> 1];
                int j0 = i0 - B_*TP_*128;
                ((float2*)g_P)[j0]         = make_float2(acc[t][u][0] + bp.x,
                                                         acc[t][u][1] + bp.y);
                ((float2*)g_P)[j0 + 8*128] = make_float2(acc[t][u][2] + bp.x,
                                                         acc[t][u][3] + bp.y);
            }
        }
    }
}

// =====================================================================
// Kernel 3: chunk-reuse assemble.
// =====================================================================
__global__ void __launch_bounds__(256) main_kernel(const float* __restrict__ pitch,
                                                   const int*   __restrict__ beats,
                                                   const float* __restrict__ Wpitch,
                                                   const float* __restrict__ bpitch,
                                                   const float* __restrict__ embBeats,
                                                   float* __restrict__ out)
{
    __shared__ __align__(16) float sP[16*E_];     // 16 KB = 1024 float4
    __shared__ int   sidx  [256];
    __shared__ float spitch[256];
    __shared__ int   sbeats[256];

    int tid = threadIdx.x;
    int t0  = blockIdx.x * 16;
    int e4  = tid & 63;
    int rp  = tid >> 6;

    #pragma unroll
    for (int i = 0; i < 4; i++)
        ((float4*)sP)[tid + i*256] = ((const float4*)g_P)[(size_t)t0*64 + tid + i*256];
    {
        int b = tid >> 4, tt = tid & 15;
        int bt = b*T_ + t0 + tt;
        sidx[tid]   = g_idx[bt];
        spitch[tid] = pitch[bt];
        sbeats[tid] = beats[bt];
    }
    __syncthreads();

    float4 wp  = ((const float4*)Wpitch)[e4];
    float4 bp  = ((const float4*)bpitch)[e4];
    float4 eb0 = ((const float4*)embBeats)[e4];
    float4 eb1 = ((const float4*)embBeats)[64 + e4];

    #pragma unroll 4
    for (int i = 0; i < 64; i++) {
        int p  = i*4 + rp;
        int b  = p >> 4, tt = p & 15;
        int ix = sidx[p];
        float4 s  = *(const float4*)&g_S[((size_t)(b*TP_ + ix))*E_ + e4*4];
        float4 pr = ((const float4*)sP)[tt*64 + e4];
        float  pv = spitch[p];
        float4 ev = sbeats[p] ? eb1 : eb0;
        float4 o;
        o.x = s.x + pr.x + fmaf(pv, wp.x, bp.x) + ev.x;
        o.y = s.y + pr.y + fmaf(pv, wp.y, bp.y) + ev.y;
        o.z = s.z + pr.z + fmaf(pv, wp.z, bp.z) + ev.z;
        o.w = s.w + pr.w + fmaf(pv, wp.w, bp.w) + ev.w;
        ((float4*)out)[((size_t)b*T_ + t0 + tt)*64 + e4] = o;
    }
}

// =====================================================================
extern "C" void kernel_launch(void* const* d_in, const int* in_sizes, int n_in,
                              void* d_out, int out_size)
{
    const float* enc      = (const float*)d_in[0];
    const int*   align_p  = (const int*)  d_in[1];
    const int*   text_p   = (const int*)  d_in[2];
    const float* pitch    = (const float*)d_in[3];
    const int*   beats    = (const int*)  d_in[4];
    const float* W_pitch  = (const float*)d_in[5];
    const float* b_pitch  = (const float*)d_in[6];
    const float* W_pos    = (const float*)d_in[7];
    const float* b_pos    = (const float*)d_in[8];
    const float* emb_b    = (const float*)d_in[9];
    float* out = (float*)d_out;

    prep_kernel<<<400, 512>>>(align_p, text_p, W_pos);

    gemm_kernel<<<M_TOT/128, 512>>>(enc, b_pos);

    main_kernel<<<T_/16, 256>>>(pitch, beats, W_pitch, b_pitch, emb_b, out);
}

// round 15
// speedup vs baseline: 1.4711x; 1.0591x over previous
#include <cuda_runtime.h>
#include <cuda_fp16.h>
#include <cstdint>

#define B_  16
#define T_  8192
#define TP_ 512
#define E_  256
#define M_TOT (B_*TP_ + T_)     // 16384 GEMM rows: 8192 enc + 8192 pe
#define FULLMASK 0xFFFFFFFFu

// ---------------- device scratch (allocations are forbidden) ----------------
__device__ __align__(16) float   g_S [B_*TP_*E_];   // enc + enc@W_pos   (8 MB)
__device__ __align__(16) float   g_P [T_*E_];       // pe@W_pos + b_pos  (8 MB)
__device__ __align__(16) int     g_idx[B_*T_];      // aligner indices   (512 KB)
__device__ __align__(16) __half  gA16[(size_t)M_TOT*E_];  // A in fp16 (8 MB)
__device__ __align__(16) __half  gBh [E_*E_];       // W^T in fp16 (128 KB)

// ---------------- helpers ----------------
// SW64 swizzle: 64-byte rows, XOR bits [5:4] with bits [8:7]
#define SWZ64(x) ((x) ^ (((x) >> 3) & 0x30))

__device__ __forceinline__ void ldsm_x4(uint32_t& r0, uint32_t& r1, uint32_t& r2,
                                        uint32_t& r3, uint32_t addr) {
    asm volatile("ldmatrix.sync.aligned.m8n8.x4.shared.b16 {%0,%1,%2,%3}, [%4];"
                 : "=r"(r0), "=r"(r1), "=r"(r2), "=r"(r3) : "r"(addr));
}
__device__ __forceinline__ uint32_t smem_u32(const void* p) {
    uint32_t a;
    asm("{ .reg .u64 t; cvta.to.shared.u64 t, %1; cvt.u32.u64 %0, t; }" : "=r"(a) : "l"(p));
    return a;
}
__device__ __forceinline__ void mma_f16(float* c, const uint32_t* a,
                                        uint32_t b0, uint32_t b1) {
    asm volatile(
        "mma.sync.aligned.m16n8k16.row.col.f32.f16.f16.f32 "
        "{%0,%1,%2,%3}, {%4,%5,%6,%7}, {%8,%9}, {%0,%1,%2,%3};"
        : "+f"(c[0]), "+f"(c[1]), "+f"(c[2]), "+f"(c[3])
        : "r"(a[0]), "r"(a[1]), "r"(a[2]), "r"(a[3]), "r"(b0), "r"(b1));
}
__device__ __forceinline__ uint32_t pack_h2(float a, float b) {
    __half2 h = __floats2half2_rn(a, b);
    return *reinterpret_cast<uint32_t*>(&h);
}

// =====================================================================
// Kernel 1 (prep):
//   blocks [0,64)      : sinusoid PE -> fp16 rows 8192+ of gA16 (32-step rot)
//   blocks [64,80)     : parallel aligner (prefix-sum + validate, exact)
//   blocks [80,208)    : W_pos transpose + fp16 convert
//   blocks [208,1232)  : enc fp32 -> fp16 rows 0..8191 of gA16
// =====================================================================
__global__ void __launch_bounds__(512) prep_kernel(const int* __restrict__ align_phone,
                                                   const int* __restrict__ text_phone,
                                                   const float* __restrict__ Wpos,
                                                   const float* __restrict__ enc)
{
    int bid = blockIdx.x, tid = threadIdx.x;

    if (bid < 64) {
        // ---- PE: 2 sincosf per 32 timesteps via rotation, fp16 out ----
        int g  = bid * 512 + tid;                  // [0, 32768)
        int i  = g & 127;                          // freq index
        int t0 = (g >> 7) * 32;                    // 256 t-blocks of 32
        const float NEGC = -0.03597789202637730f;  // -ln(10000)/E
        float div = expf((float)(2*i) * NEGC);
        float s, c, sd, cd;
        sincosf((float)t0 * div, &s, &c);
        sincosf(div, &sd, &cd);
        uint32_t* dst = (uint32_t*)gA16;           // half2 per (t, freq-pair)
        #pragma unroll
        for (int r = 0; r < 32; r++) {
            dst[(size_t)(B_*TP_ + t0 + r)*128 + i] = pack_h2(s, c);
            float s2 = fmaf(s, cd,  c*sd);
            float c2 = fmaf(c, cd, -s*sd);
            s = s2; c = c2;
        }
        return;
    }
    if (bid >= 80 && bid < 208) {
        // ---- W_pos transpose + fp16: Bt[n][k] = W[k][n] ----
        int idx = (bid - 80) * 512 + tid;          // [0, 65536)
        int k = idx >> 8, n = idx & 255;
        gBh[n*E_ + k] = __float2half_rn(Wpos[idx]);
        return;
    }
    if (bid >= 208) {
        // ---- enc fp32 -> fp16 (rows 0..8191 of gA16) ----
        int idx = (bid - 208) * 512 + tid;         // [0, 524288) float4 slots
        float4 v = ((const float4*)enc)[idx];
        uint2 h;
        h.x = pack_h2(v.x, v.y);
        h.y = pack_h2(v.z, v.w);
        ((uint2*)gA16)[idx] = h;
        return;
    }

    // ---------------- parallel aligner: block handles batch b ----------------
    __shared__ short stx[TP_];
    __shared__ int   wsum[16];
    __shared__ int   s_ok;
    int b = bid - 64;
    const int* arow = align_phone + (size_t)b * T_;
    int*       orow = g_idx       + (size_t)b * T_;

    for (int j = tid; j < TP_; j += 512) stx[j] = (short)text_phone[b*TP_ + j];
    if (tid == 0) s_ok = 1;
    __syncthreads();

    int base = tid * 16;
    int v[16];
    #pragma unroll
    for (int q = 0; q < 4; q++)
        *(int4*)&v[q*4] = *(const int4*)&arow[base + q*4];
    int prev = (base == 0) ? v[0] : arow[base - 1];

    unsigned cmask = 0;
    int cnt = 0;
    #pragma unroll
    for (int j = 0; j < 16; j++) {
        int c = (v[j] != prev) ? 1 : 0;
        if (base + j == 0) c = 0;
        cmask |= ((unsigned)c) << j;
        cnt += c;
        prev = v[j];
    }

    int lane = tid & 31, wId = tid >> 5;
    int incl = cnt;
    #pragma unroll
    for (int off = 1; off < 32; off <<= 1) {
        int nv = __shfl_up_sync(FULLMASK, incl, off);
        if (lane >= off) incl += nv;
    }
    if (lane == 31) wsum[wId] = incl;
    __syncthreads();
    if (tid == 0) {
        int a = 0;
        #pragma unroll
        for (int i = 0; i < 16; i++) { int t2 = wsum[i]; wsum[i] = a; a += t2; }
    }
    __syncthreads();
    int run = wsum[wId] + incl - cnt;

    bool ok = (base != 0) || (v[0] == (int)stx[0]);
    int outv[16];
    #pragma unroll
    for (int j = 0; j < 16; j++) {
        run += (int)((cmask >> j) & 1u);
        int ind = min(run, TP_ - 1);
        outv[j] = ind;
        if (base + j != 0) ok &= ((int)stx[ind] == v[j]);
    }
    #pragma unroll
    for (int q = 0; q < 4; q++)
        *(int4*)&orow[base + q*4] = *(const int4*)&outv[q*4];

    if (!ok) atomicAnd(&s_ok, 0);
    __syncthreads();
    if (s_ok == 0 && tid == 0) {
        int ind = 0, before = (int)stx[0];
        orow[0] = 0;
        for (int t = 1; t < T_; t++) {
            int a = arow[t];
            if (a != before) { ind = min(ind + 1, TP_ - 1); before = (int)stx[ind]; }
            orow[t] = ind;
        }
    }
}

// =====================================================================
// Kernel 2: single-pass fp16 GEMM (mma.m16n8k16, f32 acc). All operands
// pre-converted fp16 in gmem -> A and B both stream via cp.async into
// swizzled smem: 3 cp.async/thread/slice, zero LDG/STS/cvt in the hot
// loop. 3-stage pipeline (72 KB smem), one syncthreads per slice.
// CTA 128x256, grid 128 (one wave), 16 warps of 32x64, K=256 / 8 slices.
// =====================================================================
#define A_OFF 0
#define B_OFF 8192                  // A slice: 128 rows x 64B = 8 KB
#define STAGE 24576                 // + B slice: 256 rows x 64B = 16 KB
#define SMEM_GEMM (3*STAGE)         // 73728 bytes

__global__ void __launch_bounds__(512, 1) gemm_kernel(const float* __restrict__ enc,
                                                      const float* __restrict__ bpos)
{
    extern __shared__ __align__(128) char smem[];
    uint32_t sb = smem_u32(smem);

    int tid  = threadIdx.x;
    int wid  = tid >> 5, lid = tid & 31;
    int wm   = wid & 3;            // 4 m-warps of 32 rows
    int wn   = wid >> 2;           // 4 n-warps of 64 cols
    int g    = lid >> 2, tig = lid & 3;
    int mBase = blockIdx.x * 128;
    bool isEnc = (mBase < B_*TP_);

    // per-thread cp.async coordinates (fixed across slices)
    int arow = tid >> 2, ac = tid & 3;                 // A: 512 chunks of 16B
    uint32_t asw = SWZ64((uint32_t)(arow*64 + ac*16));
    int brow0 = tid >> 2, bc = tid & 3;                // B: 1024 chunks
    int brow1 = brow0 + 128;
    uint32_t bsw0 = SWZ64((uint32_t)(brow0*64 + bc*16));
    uint32_t bsw1 = SWZ64((uint32_t)(brow1*64 + bc*16));
    const uint4* Asrc = (const uint4*)gA16 + (size_t)(mBase + arow)*32 + ac;
    const uint4* Bsrc0 = (const uint4*)gBh + (size_t)brow0*32 + bc;
    const uint4* Bsrc1 = (const uint4*)gBh + (size_t)brow1*32 + bc;

    float acc[2][8][4];
    #pragma unroll
    for (int t = 0; t < 2; t++)
        #pragma unroll
        for (int u = 0; u < 8; u++)
            #pragma unroll
            for (int q = 0; q < 4; q++) acc[t][u][q] = 0.f;

    auto issue = [&](int kc, int st) {
        uint32_t base = sb + st*STAGE;
        asm volatile("cp.async.cg.shared.global [%0], [%1], 16;"
                     :: "r"(base + A_OFF + asw), "l"(Asrc + kc*4) : "memory");
        asm volatile("cp.async.cg.shared.global [%0], [%1], 16;"
                     :: "r"(base + B_OFF + bsw0), "l"(Bsrc0 + kc*4) : "memory");
        asm volatile("cp.async.cg.shared.global [%0], [%1], 16;"
                     :: "r"(base + B_OFF + bsw1), "l"(Bsrc1 + kc*4) : "memory");
        asm volatile("cp.async.commit_group;" ::: "memory");
    };

    issue(0, 0);
    issue(1, 1);

    #pragma unroll
    for (int kc = 0; kc < 8; kc++) {
        if (kc < 6) asm volatile("cp.async.wait_group 1;" ::: "memory");
        else        asm volatile("cp.async.wait_group 0;" ::: "memory");
        __syncthreads();
        if (kc + 2 < 8) issue(kc + 2, (kc + 2) % 3);

        uint32_t ab = sb + (kc % 3)*STAGE;
        #pragma unroll
        for (int ks = 0; ks < 2; ks++) {
            uint32_t ah[2][4], bh[8][2];
            #pragma unroll
            for (int t = 0; t < 2; t++) {
                uint32_t off = (uint32_t)((wm*32 + t*16 + (lid & 15))*64
                                          + ks*32 + ((lid >> 4) & 1)*16);
                ldsm_x4(ah[t][0], ah[t][1], ah[t][2], ah[t][3],
                        ab + A_OFF + SWZ64(off));
            }
            #pragma unroll
            for (int up = 0; up < 4; up++) {
                uint32_t off = (uint32_t)((wn*64 + up*16 + ((lid >> 4) & 1)*8
                                           + (lid & 7))*64
                                          + ks*32 + ((lid >> 3) & 1)*16);
                ldsm_x4(bh[2*up][0], bh[2*up][1], bh[2*up+1][0], bh[2*up+1][1],
                        ab + B_OFF + SWZ64(off));
            }
            #pragma unroll
            for (int t = 0; t < 2; t++)
                #pragma unroll
                for (int u = 0; u < 8; u++)
                    mma_f16(acc[t][u], ah[t], bh[u][0], bh[u][1]);
        }
        __syncthreads();
    }

    // ---- epilogue ----
    #pragma unroll
    for (int t = 0; t < 2; t++) {
        int rm = mBase + wm*32 + t*16 + g;
        #pragma unroll
        for (int u = 0; u < 8; u++) {
            int n  = wn*64 + u*8 + tig*2;
            int i0 = rm*128 + (n >> 1);          // float2 index, row rm
            int i1 = i0 + 8*128;                 // row rm+8
            if (isEnc) {
                float2 e0 = ((const float2*)enc)[i0];
                float2 e1 = ((const float2*)enc)[i1];
                ((float2*)g_S)[i0] = make_float2(acc[t][u][0] + e0.x,
                                                 acc[t][u][1] + e0.y);
                ((float2*)g_S)[i1] = make_float2(acc[t][u][2] + e1.x,
                                                 acc[t][u][3] + e1.y);
            } else {
                float2 bp = ((const float2*)bpos)[n >> 1];
                int j0 = i0 - B_*TP_*128;
                ((float2*)g_P)[j0]         = make_float2(acc[t][u][0] + bp.x,
                                                         acc[t][u][1] + bp.y);
                ((float2*)g_P)[j0 + 8*128] = make_float2(acc[t][u][2] + bp.x,
                                                         acc[t][u][3] + bp.y);
            }
        }
    }
}

// =====================================================================
// Kernel 3: chunk-reuse assemble.
// =====================================================================
__global__ void __launch_bounds__(256) main_kernel(const float* __restrict__ pitch,
                                                   const int*   __restrict__ beats,
                                                   const float* __restrict__ Wpitch,
                                                   const float* __restrict__ bpitch,
                                                   const float* __restrict__ embBeats,
                                                   float* __restrict__ out)
{
    __shared__ __align__(16) float sP[16*E_];     // 16 KB = 1024 float4
    __shared__ int   sidx  [256];
    __shared__ float spitch[256];
    __shared__ int   sbeats[256];

    int tid = threadIdx.x;
    int t0  = blockIdx.x * 16;
    int e4  = tid & 63;
    int rp  = tid >> 6;

    #pragma unroll
    for (int i = 0; i < 4; i++)
        ((float4*)sP)[tid + i*256] = ((const float4*)g_P)[(size_t)t0*64 + tid + i*256];
    {
        int b = tid >> 4, tt = tid & 15;
        int bt = b*T_ + t0 + tt;
        sidx[tid]   = g_idx[bt];
        spitch[tid] = pitch[bt];
        sbeats[tid] = beats[bt];
    }
    __syncthreads();

    float4 wp  = ((const float4*)Wpitch)[e4];
    float4 bp  = ((const float4*)bpitch)[e4];
    float4 eb0 = ((const float4*)embBeats)[e4];
    float4 eb1 = ((const float4*)embBeats)[64 + e4];

    #pragma unroll 4
    for (int i = 0; i < 64; i++) {
        int p  = i*4 + rp;
        int b  = p >> 4, tt = p & 15;
        int ix = sidx[p];
        float4 s  = *(const float4*)&g_S[((size_t)(b*TP_ + ix))*E_ + e4*4];
        float4 pr = ((const float4*)sP)[tt*64 + e4];
        float  pv = spitch[p];
        float4 ev = sbeats[p] ? eb1 : eb0;
        float4 o;
        o.x = s.x + pr.x + fmaf(pv, wp.x, bp.x) + ev.x;
        o.y = s.y + pr.y + fmaf(pv, wp.y, bp.y) + ev.y;
        o.z = s.z + pr.z + fmaf(pv, wp.z, bp.z) + ev.z;
        o.w = s.w + pr.w + fmaf(pv, wp.w, bp.w) + ev.w;
        ((float4*)out)[((size_t)b*T_ + t0 + tt)*64 + e4] = o;
    }
}

// =====================================================================
extern "C" void kernel_launch(void* const* d_in, const int* in_sizes, int n_in,
                              void* d_out, int out_size)
{
    const float* enc      = (const float*)d_in[0];
    const int*   align_p  = (const int*)  d_in[1];
    const int*   text_p   = (const int*)  d_in[2];
    const float* pitch    = (const float*)d_in[3];
    const int*   beats    = (const int*)  d_in[4];
    const float* W_pitch  = (const float*)d_in[5];
    const float* b_pitch  = (const float*)d_in[6];
    const float* W_pos    = (const float*)d_in[7];
    const float* b_pos    = (const float*)d_in[8];
    const float* emb_b    = (const float*)d_in[9];
    float* out = (float*)d_out;

    static int smem_set = 0;
    if (!smem_set) {
        cudaFuncSetAttribute(gemm_kernel,
                             cudaFuncAttributeMaxDynamicSharedMemorySize, SMEM_GEMM);
        smem_set = 1;
    }

    // PE (64) + aligner (16) + W (128) + enc->fp16 (1024) = 1232 blocks
    prep_kernel<<<1232, 512>>>(align_p, text_p, W_pos, enc);

    gemm_kernel<<<M_TOT/128, 512, SMEM_GEMM>>>(enc, b_pos);

    main_kernel<<<T_/16, 256>>>(pitch, beats, W_pitch, b_pitch, emb_b, out);
}

// round 16
// speedup vs baseline: 1.6118x; 1.0956x over previous
#include <cuda_runtime.h>
#include <cuda_fp16.h>
#include <cstdint>

#define B_  16
#define T_  8192
#define TP_ 512
#define E_  256
#define M_TOT (B_*TP_ + T_)     // 16384 GEMM rows: 8192 enc + 8192 pe
#define FULLMASK 0xFFFFFFFFu

// ---------------- device scratch (allocations are forbidden) ----------------
__device__ __align__(16) float   g_S [B_*TP_*E_];   // enc + enc@W_pos   (8 MB)
__device__ __align__(16) float   g_P [T_*E_];       // pe@W_pos + b_pos  (8 MB)
__device__ __align__(16) int     g_idx[B_*T_];      // aligner indices   (512 KB)
__device__ __align__(16) __half  gA16[(size_t)M_TOT*E_];  // A in fp16 (8 MB)
__device__ __align__(16) __half  gBh [E_*E_];       // W^T in fp16 (128 KB)

// ---------------- helpers ----------------
// SW128 swizzle: 128-byte rows, XOR bits [6:4] with bits [9:7]
#define SWZ128(x) ((x) ^ (((x) >> 3) & 0x70))

__device__ __forceinline__ void ldsm_x4(uint32_t& r0, uint32_t& r1, uint32_t& r2,
                                        uint32_t& r3, uint32_t addr) {
    asm volatile("ldmatrix.sync.aligned.m8n8.x4.shared.b16 {%0,%1,%2,%3}, [%4];"
                 : "=r"(r0), "=r"(r1), "=r"(r2), "=r"(r3) : "r"(addr));
}
__device__ __forceinline__ uint32_t smem_u32(const void* p) {
    uint32_t a;
    asm("{ .reg .u64 t; cvta.to.shared.u64 t, %1; cvt.u32.u64 %0, t; }" : "=r"(a) : "l"(p));
    return a;
}
__device__ __forceinline__ void mma_f16(float* c, const uint32_t* a,
                                        uint32_t b0, uint32_t b1) {
    asm volatile(
        "mma.sync.aligned.m16n8k16.row.col.f32.f16.f16.f32 "
        "{%0,%1,%2,%3}, {%4,%5,%6,%7}, {%8,%9}, {%0,%1,%2,%3};"
        : "+f"(c[0]), "+f"(c[1]), "+f"(c[2]), "+f"(c[3])
        : "r"(a[0]), "r"(a[1]), "r"(a[2]), "r"(a[3]), "r"(b0), "r"(b1));
}
__device__ __forceinline__ uint32_t pack_h2(float a, float b) {
    __half2 h = __floats2half2_rn(a, b);
    return *reinterpret_cast<uint32_t*>(&h);
}

// =====================================================================
// Kernel 1 (prep):
//   blocks [0,64)    : sinusoid PE -> fp16 rows 8192+ of gA16 (32-step rot)
//   blocks [64,80)   : parallel aligner (prefix-sum + validate, exact)
//   blocks [80,208)  : W_pos transpose + fp16 convert
//   blocks [208,464) : enc fp32 -> fp16 (4 float4 per thread)
// =====================================================================
__global__ void __launch_bounds__(512) prep_kernel(const int* __restrict__ align_phone,
                                                   const int* __restrict__ text_phone,
                                                   const float* __restrict__ Wpos,
                                                   const float* __restrict__ enc)
{
    int bid = blockIdx.x, tid = threadIdx.x;

    if (bid < 64) {
        // ---- PE: 2 sincosf per 32 timesteps via rotation, fp16 out ----
        int g  = bid * 512 + tid;                  // [0, 32768)
        int i  = g & 127;                          // freq index
        int t0 = (g >> 7) * 32;                    // 256 t-blocks of 32
        const float NEGC = -0.03597789202637730f;  // -ln(10000)/E
        float div = expf((float)(2*i) * NEGC);
        float s, c, sd, cd;
        sincosf((float)t0 * div, &s, &c);
        sincosf(div, &sd, &cd);
        uint32_t* dst = (uint32_t*)gA16;           // half2 per (t, freq-pair)
        #pragma unroll
        for (int r = 0; r < 32; r++) {
            dst[(size_t)(B_*TP_ + t0 + r)*128 + i] = pack_h2(s, c);
            float s2 = fmaf(s, cd,  c*sd);
            float c2 = fmaf(c, cd, -s*sd);
            s = s2; c = c2;
        }
        return;
    }
    if (bid >= 80 && bid < 208) {
        // ---- W_pos transpose + fp16: Bt[n][k] = W[k][n] ----
        int idx = (bid - 80) * 512 + tid;          // [0, 65536)
        int k = idx >> 8, n = idx & 255;
        gBh[n*E_ + k] = __float2half_rn(Wpos[idx]);
        return;
    }
    if (bid >= 208) {
        // ---- enc fp32 -> fp16, 4 float4 per thread for ILP ----
        int base = (bid - 208) * 2048 + tid;       // 256 blocks x 2048 slots
        #pragma unroll
        for (int q = 0; q < 4; q++) {
            int idx = base + q*512;
            float4 v = ((const float4*)enc)[idx];
            uint2 h;
            h.x = pack_h2(v.x, v.y);
            h.y = pack_h2(v.z, v.w);
            ((uint2*)gA16)[idx] = h;
        }
        return;
    }

    // ---------------- parallel aligner: block handles batch b ----------------
    __shared__ short stx[TP_];
    __shared__ int   wsum[16];
    __shared__ int   s_ok;
    int b = bid - 64;
    const int* arow = align_phone + (size_t)b * T_;
    int*       orow = g_idx       + (size_t)b * T_;

    for (int j = tid; j < TP_; j += 512) stx[j] = (short)text_phone[b*TP_ + j];
    if (tid == 0) s_ok = 1;
    __syncthreads();

    int base = tid * 16;
    int v[16];
    #pragma unroll
    for (int q = 0; q < 4; q++)
        *(int4*)&v[q*4] = *(const int4*)&arow[base + q*4];
    int prev = (base == 0) ? v[0] : arow[base - 1];

    unsigned cmask = 0;
    int cnt = 0;
    #pragma unroll
    for (int j = 0; j < 16; j++) {
        int c = (v[j] != prev) ? 1 : 0;
        if (base + j == 0) c = 0;
        cmask |= ((unsigned)c) << j;
        cnt += c;
        prev = v[j];
    }

    int lane = tid & 31, wId = tid >> 5;
    int incl = cnt;
    #pragma unroll
    for (int off = 1; off < 32; off <<= 1) {
        int nv = __shfl_up_sync(FULLMASK, incl, off);
        if (lane >= off) incl += nv;
    }
    if (lane == 31) wsum[wId] = incl;
    __syncthreads();
    if (tid == 0) {
        int a = 0;
        #pragma unroll
        for (int i = 0; i < 16; i++) { int t2 = wsum[i]; wsum[i] = a; a += t2; }
    }
    __syncthreads();
    int run = wsum[wId] + incl - cnt;

    bool ok = (base != 0) || (v[0] == (int)stx[0]);
    int outv[16];
    #pragma unroll
    for (int j = 0; j < 16; j++) {
        run += (int)((cmask >> j) & 1u);
        int ind = min(run, TP_ - 1);
        outv[j] = ind;
        if (base + j != 0) ok &= ((int)stx[ind] == v[j]);
    }
    #pragma unroll
    for (int q = 0; q < 4; q++)
        *(int4*)&orow[base + q*4] = *(const int4*)&outv[q*4];

    if (!ok) atomicAnd(&s_ok, 0);
    __syncthreads();
    if (s_ok == 0 && tid == 0) {
        int ind = 0, before = (int)stx[0];
        orow[0] = 0;
        for (int t = 1; t < T_; t++) {
            int a = arow[t];
            if (a != before) { ind = min(ind + 1, TP_ - 1); before = (int)stx[ind]; }
            orow[t] = ind;
        }
    }
}

// =====================================================================
// Kernel 2: single-pass fp16 GEMM (mma.m16n8k16, f32 acc), all operands
// cp.async'd from fp16 gmem. K=256 in 4 slices of 64 (halved sync count),
// 2-stage pipeline, 96 KB smem, SW128 swizzle (128-B rows).
// CTA 128x256, grid 128 (one wave), 16 warps of 32x64.
// =====================================================================
#define A_OFF 0
#define B_OFF 16384                 // A slice: 128 rows x 128B = 16 KB
#define STAGE 49152                 // + B slice: 256 rows x 128B = 32 KB
#define SMEM_GEMM (2*STAGE)         // 98304 bytes

__global__ void __launch_bounds__(512, 1) gemm_kernel(const float* __restrict__ enc,
                                                      const float* __restrict__ bpos)
{
    extern __shared__ __align__(128) char smem[];
    uint32_t sb = smem_u32(smem);

    int tid  = threadIdx.x;
    int wid  = tid >> 5, lid = tid & 31;
    int wm   = wid & 3;            // 4 m-warps of 32 rows
    int wn   = wid >> 2;           // 4 n-warps of 64 cols
    int g    = lid >> 2, tig = lid & 3;
    int mBase = blockIdx.x * 128;
    bool isEnc = (mBase < B_*TP_);

    float acc[2][8][4];
    #pragma unroll
    for (int t = 0; t < 2; t++)
        #pragma unroll
        for (int u = 0; u < 8; u++)
            #pragma unroll
            for (int q = 0; q < 4; q++) acc[t][u][q] = 0.f;

    // slice kc covers halves [kc*64, kc*64+64) = 8 uint4 per row
    int lrow = tid >> 3, lc = tid & 7;
    uint32_t lsw = SWZ128((uint32_t)(lrow*128 + lc*16));
    auto issue = [&](int kc, int st) {
        uint32_t base = sb + st*STAGE;
        #pragma unroll
        for (int i = 0; i < 2; i++) {           // A: 128 rows x 8 chunks
            int row = lrow + i*64;
            uint32_t off = SWZ128((uint32_t)(row*128 + lc*16));
            const uint4* src = (const uint4*)gA16 + (size_t)(mBase + row)*32
                               + kc*8 + lc;
            asm volatile("cp.async.cg.shared.global [%0], [%1], 16;"
                         :: "r"(base + A_OFF + off), "l"(src) : "memory");
        }
        #pragma unroll
        for (int i = 0; i < 4; i++) {           // B: 256 rows x 8 chunks
            int row = lrow + i*64;
            uint32_t off = SWZ128((uint32_t)(row*128 + lc*16));
            const uint4* src = (const uint4*)gBh + (size_t)row*32 + kc*8 + lc;
            asm volatile("cp.async.cg.shared.global [%0], [%1], 16;"
                         :: "r"(base + B_OFF + off), "l"(src) : "memory");
        }
        asm volatile("cp.async.commit_group;" ::: "memory");
    };
    (void)lsw;

    issue(0, 0);
    issue(1, 1);

    #pragma unroll
    for (int kc = 0; kc < 4; kc++) {
        if (kc < 3) asm volatile("cp.async.wait_group 1;" ::: "memory");
        else        asm volatile("cp.async.wait_group 0;" ::: "memory");
        __syncthreads();

        uint32_t ab = sb + (kc & 1)*STAGE;
        #pragma unroll
        for (int ks = 0; ks < 4; ks++) {        // 4 k-steps of 16 per slice
            uint32_t ah[2][4], bh[8][2];
            #pragma unroll
            for (int t = 0; t < 2; t++) {
                uint32_t off = (uint32_t)((wm*32 + t*16 + (lid & 15))*128
                                          + ks*32 + ((lid >> 4) & 1)*16);
                ldsm_x4(ah[t][0], ah[t][1], ah[t][2], ah[t][3],
                        ab + A_OFF + SWZ128(off));
            }
            #pragma unroll
            for (int up = 0; up < 4; up++) {
                uint32_t off = (uint32_t)((wn*64 + up*16 + ((lid >> 4) & 1)*8
                                           + (lid & 7))*128
                                          + ks*32 + ((lid >> 3) & 1)*16);
                ldsm_x4(bh[2*up][0], bh[2*up][1], bh[2*up+1][0], bh[2*up+1][1],
                        ab + B_OFF + SWZ128(off));
            }
            #pragma unroll
            for (int t = 0; t < 2; t++)
                #pragma unroll
                for (int u = 0; u < 8; u++)
                    mma_f16(acc[t][u], ah[t], bh[u][0], bh[u][1]);
        }
        __syncthreads();
        if (kc + 2 < 4) issue(kc + 2, kc & 1);  // refill freed stage
    }

    // ---- epilogue ----
    #pragma unroll
    for (int t = 0; t < 2; t++) {
        int rm = mBase + wm*32 + t*16 + g;
        #pragma unroll
        for (int u = 0; u < 8; u++) {
            int n  = wn*64 + u*8 + tig*2;
            int i0 = rm*128 + (n >> 1);          // float2 index, row rm
            int i1 = i0 + 8*128;                 // row rm+8
            if (isEnc) {
                float2 e0 = ((const float2*)enc)[i0];
                float2 e1 = ((const float2*)enc)[i1];
                ((float2*)g_S)[i0] = make_float2(acc[t][u][0] + e0.x,
                                                 acc[t][u][1] + e0.y);
                ((float2*)g_S)[i1] = make_float2(acc[t][u][2] + e1.x,
                                                 acc[t][u][3] + e1.y);
            } else {
                float2 bp = ((const float2*)bpos)[n >> 1];
                int j0 = i0 - B_*TP_*128;
                ((float2*)g_P)[j0]         = make_float2(acc[t][u][0] + bp.x,
                                                         acc[t][u][1] + bp.y);
                ((float2*)g_P)[j0 + 8*128] = make_float2(acc[t][u][2] + bp.x,
                                                         acc[t][u][3] + bp.y);
            }
        }
    }
}

// =====================================================================
// Kernel 3: chunk-reuse assemble (streaming stores).
// =====================================================================
__global__ void __launch_bounds__(256) main_kernel(const float* __restrict__ pitch,
                                                   const int*   __restrict__ beats,
                                                   const float* __restrict__ Wpitch,
                                                   const float* __restrict__ bpitch,
                                                   const float* __restrict__ embBeats,
                                                   float* __restrict__ out)
{
    __shared__ __align__(16) float sP[16*E_];     // 16 KB = 1024 float4
    __shared__ int   sidx  [256];
    __shared__ float spitch[256];
    __shared__ int   sbeats[256];

    int tid = threadIdx.x;
    int t0  = blockIdx.x * 16;
    int e4  = tid & 63;
    int rp  = tid >> 6;

    #pragma unroll
    for (int i = 0; i < 4; i++)
        ((float4*)sP)[tid + i*256] = ((const float4*)g_P)[(size_t)t0*64 + tid + i*256];
    {
        int b = tid >> 4, tt = tid & 15;
        int bt = b*T_ + t0 + tt;
        sidx[tid]   = g_idx[bt];
        spitch[tid] = pitch[bt];
        sbeats[tid] = beats[bt];
    }
    __syncthreads();

    float4 wp  = ((const float4*)Wpitch)[e4];
    float4 bp  = ((const float4*)bpitch)[e4];
    float4 eb0 = ((const float4*)embBeats)[e4];
    float4 eb1 = ((const float4*)embBeats)[64 + e4];

    #pragma unroll 4
    for (int i = 0; i < 64; i++) {
        int p  = i*4 + rp;
        int b  = p >> 4, tt = p & 15;
        int ix = sidx[p];
        float4 s  = *(const float4*)&g_S[((size_t)(b*TP_ + ix))*E_ + e4*4];
        float4 pr = ((const float4*)sP)[tt*64 + e4];
        float  pv = spitch[p];
        float4 ev = sbeats[p] ? eb1 : eb0;
        float4 o;
        o.x = s.x + pr.x + fmaf(pv, wp.x, bp.x) + ev.x;
        o.y = s.y + pr.y + fmaf(pv, wp.y, bp.y) + ev.y;
        o.z = s.z + pr.z + fmaf(pv, wp.z, bp.z) + ev.z;
        o.w = s.w + pr.w + fmaf(pv, wp.w, bp.w) + ev.w;
        __stcs(((float4*)out) + ((size_t)b*T_ + t0 + tt)*64 + e4, o);
    }
}

// =====================================================================
extern "C" void kernel_launch(void* const* d_in, const int* in_sizes, int n_in,
                              void* d_out, int out_size)
{
    const float* enc      = (const float*)d_in[0];
    const int*   align_p  = (const int*)  d_in[1];
    const int*   text_p   = (const int*)  d_in[2];
    const float* pitch    = (const float*)d_in[3];
    const int*   beats    = (const int*)  d_in[4];
    const float* W_pitch  = (const float*)d_in[5];
    const float* b_pitch  = (const float*)d_in[6];
    const float* W_pos    = (const float*)d_in[7];
    const float* b_pos    = (const float*)d_in[8];
    const float* emb_b    = (const float*)d_in[9];
    float* out = (float*)d_out;

    static int smem_set = 0;
    if (!smem_set) {
        cudaFuncSetAttribute(gemm_kernel,
                             cudaFuncAttributeMaxDynamicSharedMemorySize, SMEM_GEMM);
        smem_set = 1;
    }

    // PE (64) + aligner (16) + W (128) + enc->fp16 (256) = 464 blocks
    prep_kernel<<<464, 512>>>(align_p, text_p, W_pos, enc);

    gemm_kernel<<<M_TOT/128, 512, SMEM_GEMM>>>(enc, b_pos);

    main_kernel<<<T_/16, 256>>>(pitch, beats, W_pitch, b_pitch, emb_b, out);
}

// round 17
// speedup vs baseline: 1.6130x; 1.0007x over previous
#include <cuda_runtime.h>
#include <cuda_fp16.h>
#include <cstdint>

#define B_  16
#define T_  8192
#define TP_ 512
#define E_  256
#define M_TOT (B_*TP_ + T_)     // 16384 GEMM rows: 8192 enc + 8192 pe
#define FULLMASK 0xFFFFFFFFu

// ---------------- device scratch (allocations are forbidden) ----------------
__device__ __align__(16) float   g_S [B_*TP_*E_];   // enc + enc@W_pos   (8 MB)
__device__ __align__(16) float   g_P [T_*E_];       // pe@W_pos + b_pos  (8 MB)
__device__ __align__(16) int     g_idx[B_*T_];      // aligner indices   (512 KB)
__device__ __align__(16) __half  gA16[(size_t)M_TOT*E_];  // A in fp16 (8 MB)
__device__ __align__(16) __half  gBh [E_*E_];       // W^T in fp16 (128 KB)

// ---------------- helpers ----------------
// SW128 swizzle: 128-byte rows, XOR bits [6:4] with bits [9:7]
#define SWZ128(x) ((x) ^ (((x) >> 3) & 0x70))

__device__ __forceinline__ void ldsm_x4(uint32_t& r0, uint32_t& r1, uint32_t& r2,
                                        uint32_t& r3, uint32_t addr) {
    asm volatile("ldmatrix.sync.aligned.m8n8.x4.shared.b16 {%0,%1,%2,%3}, [%4];"
                 : "=r"(r0), "=r"(r1), "=r"(r2), "=r"(r3) : "r"(addr));
}
__device__ __forceinline__ uint32_t smem_u32(const void* p) {
    uint32_t a;
    asm("{ .reg .u64 t; cvta.to.shared.u64 t, %1; cvt.u32.u64 %0, t; }" : "=r"(a) : "l"(p));
    return a;
}
__device__ __forceinline__ void mma_f16(float* c, const uint32_t* a,
                                        uint32_t b0, uint32_t b1) {
    asm volatile(
        "mma.sync.aligned.m16n8k16.row.col.f32.f16.f16.f32 "
        "{%0,%1,%2,%3}, {%4,%5,%6,%7}, {%8,%9}, {%0,%1,%2,%3};"
        : "+f"(c[0]), "+f"(c[1]), "+f"(c[2]), "+f"(c[3])
        : "r"(a[0]), "r"(a[1]), "r"(a[2]), "r"(a[3]), "r"(b0), "r"(b1));
}
__device__ __forceinline__ uint32_t pack_h2(float a, float b) {
    __half2 h = __floats2half2_rn(a, b);
    return *reinterpret_cast<uint32_t*>(&h);
}

// =====================================================================
// Kernel 1 (prep):
//   blocks [0,128)   : sinusoid PE -> fp16 rows 8192+ of gA16 (16-step rot)
//   blocks [128,144) : parallel aligner (prefix-sum + validate, exact)
//   blocks [144,272) : W_pos transpose + fp16 convert
//   blocks [272,784) : enc fp32 -> fp16 (2 float4 per thread)
// =====================================================================
__global__ void __launch_bounds__(512) prep_kernel(const int* __restrict__ align_phone,
                                                   const int* __restrict__ text_phone,
                                                   const float* __restrict__ Wpos,
                                                   const float* __restrict__ enc)
{
    int bid = blockIdx.x, tid = threadIdx.x;

    if (bid < 128) {
        // ---- PE: 2 sincosf per 16 timesteps via rotation, fp16 out ----
        int g  = bid * 512 + tid;                  // [0, 65536)
        int i  = g & 127;                          // freq index
        int t0 = (g >> 7) * 16;                    // 512 t-blocks of 16
        const float NEGC = -0.03597789202637730f;  // -ln(10000)/E
        float div = expf((float)(2*i) * NEGC);
        float s, c, sd, cd;
        sincosf((float)t0 * div, &s, &c);
        sincosf(div, &sd, &cd);
        uint32_t* dst = (uint32_t*)gA16;           // half2 per (t, freq-pair)
        #pragma unroll
        for (int r = 0; r < 16; r++) {
            dst[(size_t)(B_*TP_ + t0 + r)*128 + i] = pack_h2(s, c);
            float s2 = fmaf(s, cd,  c*sd);
            float c2 = fmaf(c, cd, -s*sd);
            s = s2; c = c2;
        }
        return;
    }
    if (bid >= 144 && bid < 272) {
        // ---- W_pos transpose + fp16: Bt[n][k] = W[k][n] ----
        int idx = (bid - 144) * 512 + tid;         // [0, 65536)
        int k = idx >> 8, n = idx & 255;
        gBh[n*E_ + k] = __float2half_rn(Wpos[idx]);
        return;
    }
    if (bid >= 272) {
        // ---- enc fp32 -> fp16, 2 float4 per thread ----
        int base = (bid - 272) * 1024 + tid;       // 512 blocks x 1024 slots
        #pragma unroll
        for (int q = 0; q < 2; q++) {
            int idx = base + q*512;
            float4 v = ((const float4*)enc)[idx];
            uint2 h;
            h.x = pack_h2(v.x, v.y);
            h.y = pack_h2(v.z, v.w);
            ((uint2*)gA16)[idx] = h;
        }
        return;
    }

    // ---------------- parallel aligner: block handles batch b ----------------
    __shared__ short stx[TP_];
    __shared__ int   wsum[16];
    __shared__ int   s_ok;
    int b = bid - 128;
    const int* arow = align_phone + (size_t)b * T_;
    int*       orow = g_idx       + (size_t)b * T_;

    for (int j = tid; j < TP_; j += 512) stx[j] = (short)text_phone[b*TP_ + j];
    if (tid == 0) s_ok = 1;
    __syncthreads();

    int base = tid * 16;
    int v[16];
    #pragma unroll
    for (int q = 0; q < 4; q++)
        *(int4*)&v[q*4] = *(const int4*)&arow[base + q*4];
    int prev = (base == 0) ? v[0] : arow[base - 1];

    unsigned cmask = 0;
    int cnt = 0;
    #pragma unroll
    for (int j = 0; j < 16; j++) {
        int c = (v[j] != prev) ? 1 : 0;
        if (base + j == 0) c = 0;
        cmask |= ((unsigned)c) << j;
        cnt += c;
        prev = v[j];
    }

    int lane = tid & 31, wId = tid >> 5;
    int incl = cnt;
    #pragma unroll
    for (int off = 1; off < 32; off <<= 1) {
        int nv = __shfl_up_sync(FULLMASK, incl, off);
        if (lane >= off) incl += nv;
    }
    if (lane == 31) wsum[wId] = incl;
    __syncthreads();
    if (tid == 0) {
        int a = 0;
        #pragma unroll
        for (int i = 0; i < 16; i++) { int t2 = wsum[i]; wsum[i] = a; a += t2; }
    }
    __syncthreads();
    int run = wsum[wId] + incl - cnt;

    bool ok = (base != 0) || (v[0] == (int)stx[0]);
    int outv[16];
    #pragma unroll
    for (int j = 0; j < 16; j++) {
        run += (int)((cmask >> j) & 1u);
        int ind = min(run, TP_ - 1);
        outv[j] = ind;
        if (base + j != 0) ok &= ((int)stx[ind] == v[j]);
    }
    #pragma unroll
    for (int q = 0; q < 4; q++)
        *(int4*)&orow[base + q*4] = *(const int4*)&outv[q*4];

    if (!ok) atomicAnd(&s_ok, 0);
    __syncthreads();
    if (s_ok == 0 && tid == 0) {
        int ind = 0, before = (int)stx[0];
        orow[0] = 0;
        for (int t = 1; t < T_; t++) {
            int a = arow[t];
            if (a != before) { ind = min(ind + 1, TP_ - 1); before = (int)stx[ind]; }
            orow[t] = ind;
        }
    }
}

// =====================================================================
// Kernel 2: single-pass fp16 GEMM (mma.m16n8k16, f32 acc). ALL operands
// resident in smem (4 slices x (16 KB A + 32 KB B) = 192 KB): every
// cp.async issued up front in 4 commit-groups (max MLP, no refills, no
// buffer reuse -> one syncthreads per slice, 4 total). SW128 swizzle.
// CTA 128x256, grid 128 (one wave), 16 warps of 32x64.
// =====================================================================
#define A_OFF 0
#define B_OFF 16384                 // A slice: 128 rows x 128B = 16 KB
#define STAGE 49152                 // + B slice: 256 rows x 128B = 32 KB
#define SMEM_GEMM (4*STAGE)         // 196608 bytes

__global__ void __launch_bounds__(512, 1) gemm_kernel(const float* __restrict__ enc,
                                                      const float* __restrict__ bpos)
{
    extern __shared__ __align__(128) char smem[];
    uint32_t sb = smem_u32(smem);

    int tid  = threadIdx.x;
    int wid  = tid >> 5, lid = tid & 31;
    int wm   = wid & 3;            // 4 m-warps of 32 rows
    int wn   = wid >> 2;           // 4 n-warps of 64 cols
    int g    = lid >> 2, tig = lid & 3;
    int mBase = blockIdx.x * 128;
    bool isEnc = (mBase < B_*TP_);

    float acc[2][8][4];
    #pragma unroll
    for (int t = 0; t < 2; t++)
        #pragma unroll
        for (int u = 0; u < 8; u++)
            #pragma unroll
            for (int q = 0; q < 4; q++) acc[t][u][q] = 0.f;

    // issue ALL loads up front: slice kc = group kc
    int lrow = tid >> 3, lc = tid & 7;
    #pragma unroll
    for (int kc = 0; kc < 4; kc++) {
        uint32_t base = sb + kc*STAGE;
        #pragma unroll
        for (int i = 0; i < 2; i++) {           // A: 128 rows x 8 chunks
            int row = lrow + i*64;
            uint32_t off = SWZ128((uint32_t)(row*128 + lc*16));
            const uint4* src = (const uint4*)gA16 + (size_t)(mBase + row)*32
                               + kc*8 + lc;
            asm volatile("cp.async.cg.shared.global [%0], [%1], 16;"
                         :: "r"(base + A_OFF + off), "l"(src) : "memory");
        }
        #pragma unroll
        for (int i = 0; i < 4; i++) {           // B: 256 rows x 8 chunks
            int row = lrow + i*64;
            uint32_t off = SWZ128((uint32_t)(row*128 + lc*16));
            const uint4* src = (const uint4*)gBh + (size_t)row*32 + kc*8 + lc;
            asm volatile("cp.async.cg.shared.global [%0], [%1], 16;"
                         :: "r"(base + B_OFF + off), "l"(src) : "memory");
        }
        asm volatile("cp.async.commit_group;" ::: "memory");
    }

    #pragma unroll
    for (int kc = 0; kc < 4; kc++) {
        switch (kc) {                            // groups 0..kc complete
            case 0: asm volatile("cp.async.wait_group 3;" ::: "memory"); break;
            case 1: asm volatile("cp.async.wait_group 2;" ::: "memory"); break;
            case 2: asm volatile("cp.async.wait_group 1;" ::: "memory"); break;
            default: asm volatile("cp.async.wait_group 0;" ::: "memory"); break;
        }
        __syncthreads();

        uint32_t ab = sb + kc*STAGE;
        #pragma unroll
        for (int ks = 0; ks < 4; ks++) {        // 4 k-steps of 16 per slice
            uint32_t ah[2][4], bh[8][2];
            #pragma unroll
            for (int t = 0; t < 2; t++) {
                uint32_t off = (uint32_t)((wm*32 + t*16 + (lid & 15))*128
                                          + ks*32 + ((lid >> 4) & 1)*16);
                ldsm_x4(ah[t][0], ah[t][1], ah[t][2], ah[t][3],
                        ab + A_OFF + SWZ128(off));
            }
            #pragma unroll
            for (int up = 0; up < 4; up++) {
                uint32_t off = (uint32_t)((wn*64 + up*16 + ((lid >> 4) & 1)*8
                                           + (lid & 7))*128
                                          + ks*32 + ((lid >> 3) & 1)*16);
                ldsm_x4(bh[2*up][0], bh[2*up][1], bh[2*up+1][0], bh[2*up+1][1],
                        ab + B_OFF + SWZ128(off));
            }
            #pragma unroll
            for (int t = 0; t < 2; t++)
                #pragma unroll
                for (int u = 0; u < 8; u++)
                    mma_f16(acc[t][u], ah[t], bh[u][0], bh[u][1]);
        }
        // no trailing sync: buffers are never reused
    }

    // ---- epilogue ----
    #pragma unroll
    for (int t = 0; t < 2; t++) {
        int rm = mBase + wm*32 + t*16 + g;
        #pragma unroll
        for (int u = 0; u < 8; u++) {
            int n  = wn*64 + u*8 + tig*2;
            int i0 = rm*128 + (n >> 1);          // float2 index, row rm
            int i1 = i0 + 8*128;                 // row rm+8
            if (isEnc) {
                float2 e0 = ((const float2*)enc)[i0];
                float2 e1 = ((const float2*)enc)[i1];
                ((float2*)g_S)[i0] = make_float2(acc[t][u][0] + e0.x,
                                                 acc[t][u][1] + e0.y);
                ((float2*)g_S)[i1] = make_float2(acc[t][u][2] + e1.x,
                                                 acc[t][u][3] + e1.y);
            } else {
                float2 bp = ((const float2*)bpos)[n >> 1];
                int j0 = i0 - B_*TP_*128;
                ((float2*)g_P)[j0]         = make_float2(acc[t][u][0] + bp.x,
                                                         acc[t][u][1] + bp.y);
                ((float2*)g_P)[j0 + 8*128] = make_float2(acc[t][u][2] + bp.x,
                                                         acc[t][u][3] + bp.y);
            }
        }
    }
}

// =====================================================================
// Kernel 3: chunk-reuse assemble (streaming stores).
// =====================================================================
__global__ void __launch_bounds__(256) main_kernel(const float* __restrict__ pitch,
                                                   const int*   __restrict__ beats,
                                                   const float* __restrict__ Wpitch,
                                                   const float* __restrict__ bpitch,
                                                   const float* __restrict__ embBeats,
                                                   float* __restrict__ out)
{
    __shared__ __align__(16) float sP[16*E_];     // 16 KB = 1024 float4
    __shared__ int   sidx  [256];
    __shared__ float spitch[256];
    __shared__ int   sbeats[256];

    int tid = threadIdx.x;
    int t0  = blockIdx.x * 16;
    int e4  = tid & 63;
    int rp  = tid >> 6;

    #pragma unroll
    for (int i = 0; i < 4; i++)
        ((float4*)sP)[tid + i*256] = ((const float4*)g_P)[(size_t)t0*64 + tid + i*256];
    {
        int b = tid >> 4, tt = tid & 15;
        int bt = b*T_ + t0 + tt;
        sidx[tid]   = g_idx[bt];
        spitch[tid] = pitch[bt];
        sbeats[tid] = beats[bt];
    }
    __syncthreads();

    float4 wp  = ((const float4*)Wpitch)[e4];
    float4 bp  = ((const float4*)bpitch)[e4];
    float4 eb0 = ((const float4*)embBeats)[e4];
    float4 eb1 = ((const float4*)embBeats)[64 + e4];

    #pragma unroll 4
    for (int i = 0; i < 64; i++) {
        int p  = i*4 + rp;
        int b  = p >> 4, tt = p & 15;
        int ix = sidx[p];
        float4 s  = *(const float4*)&g_S[((size_t)(b*TP_ + ix))*E_ + e4*4];
        float4 pr = ((const float4*)sP)[tt*64 + e4];
        float  pv = spitch[p];
        float4 ev = sbeats[p] ? eb1 : eb0;
        float4 o;
        o.x = s.x + pr.x + fmaf(pv, wp.x, bp.x) + ev.x;
        o.y = s.y + pr.y + fmaf(pv, wp.y, bp.y) + ev.y;
        o.z = s.z + pr.z + fmaf(pv, wp.z, bp.z) + ev.z;
        o.w = s.w + pr.w + fmaf(pv, wp.w, bp.w) + ev.w;
        __stcs(((float4*)out) + ((size_t)b*T_ + t0 + tt)*64 + e4, o);
    }
}

// =====================================================================
extern "C" void kernel_launch(void* const* d_in, const int* in_sizes, int n_in,
                              void* d_out, int out_size)
{
    const float* enc      = (const float*)d_in[0];
    const int*   align_p  = (const int*)  d_in[1];
    const int*   text_p   = (const int*)  d_in[2];
    const float* pitch    = (const float*)d_in[3];
    const int*   beats    = (const int*)  d_in[4];
    const float* W_pitch  = (const float*)d_in[5];
    const float* b_pitch  = (const float*)d_in[6];
    const float* W_pos    = (const float*)d_in[7];
    const float* b_pos    = (const float*)d_in[8];
    const float* emb_b    = (const float*)d_in[9];
    float* out = (float*)d_out;

    static int smem_set = 0;
    if (!smem_set) {
        cudaFuncSetAttribute(gemm_kernel,
                             cudaFuncAttributeMaxDynamicSharedMemorySize, SMEM_GEMM);
        smem_set = 1;
    }

    // PE (128) + aligner (16) + W (128) + enc->fp16 (512) = 784 blocks
    prep_kernel<<<784, 512>>>(align_p, text_p, W_pos, enc);

    gemm_kernel<<<M_TOT/128, 512, SMEM_GEMM>>>(enc, b_pos);

    main_kernel<<<T_/16, 256>>>(pitch, beats, W_pitch, b_pitch, emb_b, out);
}